// round 1
// baseline (speedup 1.0000x reference)
#include <cuda_runtime.h>
#include <cuda_bf16.h>
#include <math.h>

// ---------------- problem constants ----------------
constexpr int B_    = 16;
constexpr int C_    = 512;
constexpr int H_    = 56;
constexpr int W_    = 56;
constexpr int NTOK  = H_ * W_;        // 3136
constexpr int MTOK  = B_ * NTOK;      // 50176
constexpr int HEADS = 8;
constexpr int HD    = 64;
constexpr int AG    = 49;             // agent tokens

// ---------------- scratch (device globals: allocation-free) ----------------
__device__ float g_q [MTOK * C_];
__device__ float g_k [MTOK * C_];
__device__ float g_v [MTOK * C_];
__device__ float g_ao[MTOK * C_];                 // attention output + dwc (pre-proj)
__device__ float g_logits[B_ * HEADS * AG * NTOK]; // agent attn logits / probs
__device__ float g_at[B_ * AG * C_];               // agent tokens
__device__ float g_av[B_ * HEADS * AG * HD];       // agent_v
__device__ float g_bias_agent[HEADS * AG * NTOK];  // pb1 + pb2  [h][a][n]
__device__ float g_bias_q    [HEADS * NTOK * AG];  // ab1 + ab2  [h][n][a]

// ---------------- bilinear (jax.image.resize 7 -> 56, clamp-edge) ----------------
__device__ __forceinline__ float bilerp7(const float* t, int y0, int y1, float wy,
                                         int x0, int x1, float wx) {
    float v00 = t[y0 * 7 + x0], v01 = t[y0 * 7 + x1];
    float v10 = t[y1 * 7 + x0], v11 = t[y1 * 7 + x1];
    float a = v00 + (v01 - v00) * wx;
    float b = v10 + (v11 - v10) * wx;
    return a + (b - a) * wy;
}

// K0: precompute both positional-bias tables
__global__ __launch_bounds__(256) void k_bias(
    const float* __restrict__ an, const float* __restrict__ na,
    const float* __restrict__ ahb, const float* __restrict__ awb,
    const float* __restrict__ hab, const float* __restrict__ wab)
{
    int idx = blockIdx.x * 256 + threadIdx.x;          // over HEADS*NTOK = 25088
    if (idx >= HEADS * NTOK) return;
    int h = idx / NTOK;
    int n = idx % NTOK;
    int y = n / W_, x = n % W_;

    float fy = (y + 0.5f) * 0.125f - 0.5f;
    int iy = (int)floorf(fy);
    float wy = fy - (float)iy;
    int y0 = max(iy, 0), y1 = min(iy + 1, 6);

    float fx = (x + 0.5f) * 0.125f - 0.5f;
    int ix = (int)floorf(fx);
    float wx = fx - (float)ix;
    int x0 = max(ix, 0), x1 = min(ix + 1, 6);

    for (int a = 0; a < AG; a++) {
        const float* t1 = an + ((size_t)h * AG + a) * 49;
        float v1 = bilerp7(t1, y0, y1, wy, x0, x1, wx);
        g_bias_agent[((size_t)h * AG + a) * NTOK + n] =
            v1 + ahb[((size_t)h * AG + a) * W_ + y] + awb[((size_t)h * AG + a) * W_ + x];

        const float* t2 = na + ((size_t)h * AG + a) * 49;
        float v2 = bilerp7(t2, y0, y1, wy, x0, x1, wx);
        g_bias_q[((size_t)h * NTOK + n) * AG + a] =
            v2 + hab[((size_t)h * W_ + y) * AG + a] + wab[((size_t)h * W_ + x) * AG + a];
    }
}

// ---------------- SGEMM core: C(M,N) = A(M,K) * W(N,K)^T, 128x128x8 tiles ----------------
// K1: fused QKV  (N = 1536 split across q_w rows + kv_w rows)
__global__ __launch_bounds__(256) void sgemm_qkv(
    const float* __restrict__ A, const float* __restrict__ qw, const float* __restrict__ kvw)
{
    const int K = C_;
    __shared__ __align__(16) float As[8][128];
    __shared__ __align__(16) float Bs[8][128];

    int tid = threadIdx.x;
    int bm = blockIdx.y, bn = blockIdx.x;
    const float* Ab = A + (size_t)bm * 128 * K;

    int j0 = bn * 128;
    const float* Wm; float* O; int colbase;
    if (j0 < 512)        { Wm = qw  + (size_t)j0 * K;          O = g_q; colbase = j0; }
    else if (j0 < 1024)  { Wm = kvw + (size_t)(j0 - 512) * K;  O = g_k; colbase = j0 - 512; }
    else                 { Wm = kvw + (size_t)(j0 - 512) * K;  O = g_v; colbase = j0 - 1024; }

    int lr = tid >> 1, lc = (tid & 1) * 4;
    int tx = tid & 15, ty = tid >> 4;

    float acc[8][8] = {};

    for (int k0 = 0; k0 < K; k0 += 8) {
        float4 a4 = *(const float4*)(Ab + (size_t)lr * K + k0 + lc);
        float4 b4 = *(const float4*)(Wm + (size_t)lr * K + k0 + lc);
        As[lc + 0][lr] = a4.x; As[lc + 1][lr] = a4.y; As[lc + 2][lr] = a4.z; As[lc + 3][lr] = a4.w;
        Bs[lc + 0][lr] = b4.x; Bs[lc + 1][lr] = b4.y; Bs[lc + 2][lr] = b4.z; Bs[lc + 3][lr] = b4.w;
        __syncthreads();
        #pragma unroll
        for (int kk = 0; kk < 8; kk++) {
            float4 a0 = *(const float4*)&As[kk][ty * 8];
            float4 a1 = *(const float4*)&As[kk][ty * 8 + 4];
            float4 b0 = *(const float4*)&Bs[kk][tx * 8];
            float4 b1 = *(const float4*)&Bs[kk][tx * 8 + 4];
            float ar[8] = {a0.x, a0.y, a0.z, a0.w, a1.x, a1.y, a1.z, a1.w};
            float br[8] = {b0.x, b0.y, b0.z, b0.w, b1.x, b1.y, b1.z, b1.w};
            #pragma unroll
            for (int ii = 0; ii < 8; ii++)
                #pragma unroll
                for (int jj = 0; jj < 8; jj++)
                    acc[ii][jj] += ar[ii] * br[jj];
        }
        __syncthreads();
    }

    #pragma unroll
    for (int ii = 0; ii < 8; ii++) {
        int row = bm * 128 + ty * 8 + ii;
        float* op = O + (size_t)row * 512 + colbase + tx * 8;
        *(float4*)(op)     = make_float4(acc[ii][0], acc[ii][1], acc[ii][2], acc[ii][3]);
        *(float4*)(op + 4) = make_float4(acc[ii][4], acc[ii][5], acc[ii][6], acc[ii][7]);
    }
}

// K8: projection GEMM (+bias) writing final output
__global__ __launch_bounds__(256) void sgemm_proj(
    const float* __restrict__ pw, const float* __restrict__ pb, float* __restrict__ out)
{
    const int K = C_;
    __shared__ __align__(16) float As[8][128];
    __shared__ __align__(16) float Bs[8][128];

    int tid = threadIdx.x;
    int bm = blockIdx.y, bn = blockIdx.x;
    const float* Ab = g_ao + (size_t)bm * 128 * K;
    const float* Wm = pw + (size_t)bn * 128 * K;
    int colbase = bn * 128;

    int lr = tid >> 1, lc = (tid & 1) * 4;
    int tx = tid & 15, ty = tid >> 4;

    float acc[8][8] = {};

    for (int k0 = 0; k0 < K; k0 += 8) {
        float4 a4 = *(const float4*)(Ab + (size_t)lr * K + k0 + lc);
        float4 b4 = *(const float4*)(Wm + (size_t)lr * K + k0 + lc);
        As[lc + 0][lr] = a4.x; As[lc + 1][lr] = a4.y; As[lc + 2][lr] = a4.z; As[lc + 3][lr] = a4.w;
        Bs[lc + 0][lr] = b4.x; Bs[lc + 1][lr] = b4.y; Bs[lc + 2][lr] = b4.z; Bs[lc + 3][lr] = b4.w;
        __syncthreads();
        #pragma unroll
        for (int kk = 0; kk < 8; kk++) {
            float4 a0 = *(const float4*)&As[kk][ty * 8];
            float4 a1 = *(const float4*)&As[kk][ty * 8 + 4];
            float4 b0 = *(const float4*)&Bs[kk][tx * 8];
            float4 b1 = *(const float4*)&Bs[kk][tx * 8 + 4];
            float ar[8] = {a0.x, a0.y, a0.z, a0.w, a1.x, a1.y, a1.z, a1.w};
            float br[8] = {b0.x, b0.y, b0.z, b0.w, b1.x, b1.y, b1.z, b1.w};
            #pragma unroll
            for (int ii = 0; ii < 8; ii++)
                #pragma unroll
                for (int jj = 0; jj < 8; jj++)
                    acc[ii][jj] += ar[ii] * br[jj];
        }
        __syncthreads();
    }

    #pragma unroll
    for (int ii = 0; ii < 8; ii++) {
        int row = bm * 128 + ty * 8 + ii;
        float* op = out + (size_t)row * 512 + colbase + tx * 8;
        #pragma unroll
        for (int jj = 0; jj < 8; jj++) acc[ii][jj] += pb[colbase + tx * 8 + jj];
        *(float4*)(op)     = make_float4(acc[ii][0], acc[ii][1], acc[ii][2], acc[ii][3]);
        *(float4*)(op + 4) = make_float4(acc[ii][4], acc[ii][5], acc[ii][6], acc[ii][7]);
    }
}

// K2: agent token pooling: 8x8 mean over q_img (B,H,W,C) -> (B,49,C)
__global__ __launch_bounds__(256) void k_pool()
{
    int idx = blockIdx.x * 256 + threadIdx.x;   // over B_*AG*C_ = 401408
    int c = idx & 511;
    int a = (idx >> 9) % AG;
    int b = idx / (AG * C_);
    int ay = a / 7, ax = a % 7;
    float s = 0.f;
    #pragma unroll
    for (int dy = 0; dy < 8; dy++)
        for (int dx = 0; dx < 8; dx++)
            s += g_q[((size_t)(b * NTOK + (ay * 8 + dy) * W_ + ax * 8 + dx)) * C_ + c];
    g_at[idx] = s * (1.0f / 64.0f);
}

// K3: agent logits (b,h): logits[a][n] = scale*<ah_a, k_n> + bias_agent[h][a][n]
__global__ __launch_bounds__(256) void k_agent_logits()
{
    int bh = blockIdx.y;
    int b = bh >> 3, h = bh & 7;
    __shared__ __align__(16) float s_ah[AG * HD];
    for (int i = threadIdx.x; i < AG * HD; i += 256) {
        int a = i >> 6, d = i & 63;
        s_ah[i] = g_at[((size_t)b * AG + a) * C_ + h * HD + d] * 0.125f;
    }
    __syncthreads();

    int n = blockIdx.x * 256 + threadIdx.x;
    if (n >= NTOK) return;

    const float4* kp = (const float4*)(g_k + ((size_t)(b * NTOK + n)) * C_ + h * HD);
    float4 kr[16];
    #pragma unroll
    for (int i = 0; i < 16; i++) kr[i] = kp[i];

    const float4* ah4 = (const float4*)s_ah;
    for (int a = 0; a < AG; a++) {
        float acc = g_bias_agent[((size_t)h * AG + a) * NTOK + n];
        #pragma unroll
        for (int i = 0; i < 16; i++) {
            float4 av = ah4[a * 16 + i];
            acc += kr[i].x * av.x + kr[i].y * av.y + kr[i].z * av.z + kr[i].w * av.w;
        }
        g_logits[((size_t)bh * AG + a) * NTOK + n] = acc;
    }
}

// K4: softmax over n=3136 per (b,h,a) row, in-place on g_logits
__global__ __launch_bounds__(256) void k_softmax()
{
    float* row = g_logits + (size_t)blockIdx.x * NTOK;
    __shared__ float red[256];
    int t = threadIdx.x;

    float m = -1e30f;
    for (int i = t; i < NTOK; i += 256) m = fmaxf(m, row[i]);
    red[t] = m; __syncthreads();
    for (int s = 128; s > 0; s >>= 1) { if (t < s) red[t] = fmaxf(red[t], red[t + s]); __syncthreads(); }
    m = red[0]; __syncthreads();

    float sum = 0.f;
    for (int i = t; i < NTOK; i += 256) { float e = __expf(row[i] - m); row[i] = e; sum += e; }
    red[t] = sum; __syncthreads();
    for (int s = 128; s > 0; s >>= 1) { if (t < s) red[t] += red[t + s]; __syncthreads(); }
    float inv = 1.0f / red[0];

    for (int i = t; i < NTOK; i += 256) row[i] *= inv;
}

// K5: agent_v[b,h,a,d] = sum_n attn[a][n] * v[b,n,h*64+d]
__global__ __launch_bounds__(256) void k_agent_v()
{
    int bh = blockIdx.x;
    int b = bh >> 3, h = bh & 7;
    __shared__ float s_at[AG][64];
    __shared__ float s_v[64][64];
    int tid = threadIdx.x;
    int d = tid & 63;
    int as = tid >> 6;   // 0..3

    float acc[13];
    #pragma unroll
    for (int j = 0; j < 13; j++) acc[j] = 0.f;

    for (int n0 = 0; n0 < NTOK; n0 += 64) {
        for (int i = tid; i < 64 * 64; i += 256) {
            int r = i >> 6, c = i & 63;
            s_v[r][c] = g_v[((size_t)(b * NTOK + n0 + r)) * C_ + h * HD + c];
        }
        for (int i = tid; i < AG * 64; i += 256) {
            int a = i >> 6, c = i & 63;
            s_at[a][c] = g_logits[((size_t)bh * AG + a) * NTOK + n0 + c];
        }
        __syncthreads();
        for (int nn = 0; nn < 64; nn++) {
            float vv = s_v[nn][d];
            #pragma unroll
            for (int j = 0; j < 13; j++) {
                int a = as + j * 4;
                if (a < AG) acc[j] += s_at[a][nn] * vv;
            }
        }
        __syncthreads();
    }
    #pragma unroll
    for (int j = 0; j < 13; j++) {
        int a = as + j * 4;
        if (a < AG) g_av[((size_t)bh * AG + a) * HD + d] = acc[j];
    }
}

// K6: q-attention (softmax over 49 agents) fully fused per token
__global__ __launch_bounds__(128) void k_qattn()
{
    int bh = blockIdx.y;
    int b = bh >> 3, h = bh & 7;
    __shared__ __align__(16) float s_ah[AG * HD];
    __shared__ __align__(16) float s_av[AG * HD];
    for (int i = threadIdx.x; i < AG * HD; i += 128) {
        int a = i >> 6, d = i & 63;
        s_ah[i] = g_at[((size_t)b * AG + a) * C_ + h * HD + d];
        s_av[i] = g_av[((size_t)bh * AG + a) * HD + d];
    }
    __syncthreads();

    int n = blockIdx.x * 128 + threadIdx.x;
    if (n >= NTOK) return;

    const float4* qp = (const float4*)(g_q + ((size_t)(b * NTOK + n)) * C_ + h * HD);
    float4 qr[16];
    #pragma unroll
    for (int i = 0; i < 16; i++) {
        float4 t = qp[i];
        t.x *= 0.125f; t.y *= 0.125f; t.z *= 0.125f; t.w *= 0.125f;
        qr[i] = t;
    }

    const float* bq = g_bias_q + ((size_t)h * NTOK + n) * AG;
    float lg[AG];
    float m = -1e30f;
    const float4* ah4 = (const float4*)s_ah;
    for (int a = 0; a < AG; a++) {
        float acc = bq[a];
        #pragma unroll
        for (int i = 0; i < 16; i++) {
            float4 av = ah4[a * 16 + i];
            acc += qr[i].x * av.x + qr[i].y * av.y + qr[i].z * av.z + qr[i].w * av.w;
        }
        lg[a] = acc;
        m = fmaxf(m, acc);
    }
    float s = 0.f;
    for (int a = 0; a < AG; a++) { float e = __expf(lg[a] - m); lg[a] = e; s += e; }
    float inv = 1.0f / s;

    float4 o[16];
    #pragma unroll
    for (int i = 0; i < 16; i++) o[i] = make_float4(0.f, 0.f, 0.f, 0.f);
    const float4* av4 = (const float4*)s_av;
    for (int a = 0; a < AG; a++) {
        float w = lg[a] * inv;
        #pragma unroll
        for (int i = 0; i < 16; i++) {
            float4 v = av4[a * 16 + i];
            o[i].x += w * v.x; o[i].y += w * v.y; o[i].z += w * v.z; o[i].w += w * v.w;
        }
    }
    float4* op = (float4*)(g_ao + ((size_t)(b * NTOK + n)) * C_ + h * HD);
    #pragma unroll
    for (int i = 0; i < 16; i++) op[i] = o[i];
}

// K7: depthwise 3x3 conv on v (as NCHW via index math), accumulate into g_ao
__global__ __launch_bounds__(256) void k_dwc(const float* __restrict__ w, const float* __restrict__ bias)
{
    int idx = blockIdx.x * 256 + threadIdx.x;   // over MTOK*C_
    int c = idx & 511;
    int n = (idx >> 9) % NTOK;
    int b = idx / (NTOK * C_);
    int y = n / W_, x = n % W_;

    float acc = bias[c];
    #pragma unroll
    for (int dy = -1; dy <= 1; dy++) {
        int yy = y + dy;
        if (yy < 0 || yy >= H_) continue;
        #pragma unroll
        for (int dx = -1; dx <= 1; dx++) {
            int xx = x + dx;
            if (xx < 0 || xx >= W_) continue;
            acc += g_v[((size_t)(b * NTOK + yy * W_ + xx)) * C_ + c] * w[c * 9 + (dy + 1) * 3 + (dx + 1)];
        }
    }
    g_ao[idx] += acc;
}

// ---------------- launch ----------------
extern "C" void kernel_launch(void* const* d_in, const int* in_sizes, int n_in,
                              void* d_out, int out_size)
{
    // Inputs: x, [H, W scalars?], q_w, kv_w, proj_w, proj_b, dwc_w, dwc_b,
    //         an_bias, na_bias, ah_bias, aw_bias, ha_bias, wa_bias
    int base = (n_in >= 15 && in_sizes[1] == 1) ? 3 : 1;

    const float* x      = (const float*)d_in[0];
    const float* q_w    = (const float*)d_in[base + 0];
    const float* kv_w   = (const float*)d_in[base + 1];
    const float* proj_w = (const float*)d_in[base + 2];
    const float* proj_b = (const float*)d_in[base + 3];
    const float* dwc_w  = (const float*)d_in[base + 4];
    const float* dwc_b  = (const float*)d_in[base + 5];
    const float* an_b   = (const float*)d_in[base + 6];
    const float* na_b   = (const float*)d_in[base + 7];
    const float* ah_b   = (const float*)d_in[base + 8];
    const float* aw_b   = (const float*)d_in[base + 9];
    const float* ha_b   = (const float*)d_in[base + 10];
    const float* wa_b   = (const float*)d_in[base + 11];
    float* out = (float*)d_out;

    k_bias<<<98, 256>>>(an_b, na_b, ah_b, aw_b, ha_b, wa_b);
    sgemm_qkv<<<dim3(12, MTOK / 128), 256>>>(x, q_w, kv_w);
    k_pool<<<(B_ * AG * C_) / 256, 256>>>();
    k_agent_logits<<<dim3((NTOK + 255) / 256, B_ * HEADS), 256>>>();
    k_softmax<<<B_ * HEADS * AG, 256>>>();
    k_agent_v<<<B_ * HEADS, 256>>>();
    k_qattn<<<dim3((NTOK + 127) / 128, B_ * HEADS), 128>>>();
    k_dwc<<<(MTOK * C_) / 256, 256>>>(dwc_w, dwc_b);
    sgemm_proj<<<dim3(4, MTOK / 128), 256>>>(proj_w, proj_b, out);
}

// round 4
// speedup vs baseline: 1.2127x; 1.2127x over previous
#include <cuda_runtime.h>
#include <cuda_bf16.h>
#include <math.h>

// ---------------- problem constants ----------------
constexpr int B_    = 16;
constexpr int C_    = 512;
constexpr int H_    = 56;
constexpr int W_    = 56;
constexpr int NTOK  = H_ * W_;        // 3136
constexpr int MTOK  = B_ * NTOK;      // 50176
constexpr int HEADS = 8;
constexpr int HD    = 64;
constexpr int AG    = 49;             // agent tokens

// ---------------- scratch (device globals: allocation-free) ----------------
__device__ float g_q [MTOK * C_];
__device__ float g_k [MTOK * C_];
__device__ float g_v [MTOK * C_];
__device__ float g_ao[MTOK * C_];                 // attention output + dwc (pre-proj)
__device__ float g_logits[B_ * HEADS * AG * NTOK]; // agent attn logits / probs
__device__ float g_at[B_ * AG * C_];               // agent tokens
__device__ float g_av[B_ * HEADS * AG * HD];       // agent_v
__device__ float g_bias_agent[HEADS * AG * NTOK];  // pb1 + pb2  [h][a][n]
__device__ float g_bias_q    [HEADS * NTOK * AG];  // ab1 + ab2  [h][n][a]

// ---------------- bilinear (jax.image.resize 7 -> 56, clamp-edge) ----------------
__device__ __forceinline__ float bilerp7(const float* t, int y0, int y1, float wy,
                                         int x0, int x1, float wx) {
    float v00 = t[y0 * 7 + x0], v01 = t[y0 * 7 + x1];
    float v10 = t[y1 * 7 + x0], v11 = t[y1 * 7 + x1];
    float a = v00 + (v01 - v00) * wx;
    float b = v10 + (v11 - v10) * wx;
    return a + (b - a) * wy;
}

// K0: precompute both positional-bias tables
__global__ __launch_bounds__(256) void k_bias(
    const float* __restrict__ an, const float* __restrict__ na,
    const float* __restrict__ ahb, const float* __restrict__ awb,
    const float* __restrict__ hab, const float* __restrict__ wab)
{
    int idx = blockIdx.x * 256 + threadIdx.x;          // over HEADS*NTOK = 25088
    if (idx >= HEADS * NTOK) return;
    int h = idx / NTOK;
    int n = idx % NTOK;
    int y = n / W_, x = n % W_;

    float fy = (y + 0.5f) * 0.125f - 0.5f;
    int iy = (int)floorf(fy);
    float wy = fy - (float)iy;
    int y0 = max(iy, 0), y1 = min(iy + 1, 6);

    float fx = (x + 0.5f) * 0.125f - 0.5f;
    int ix = (int)floorf(fx);
    float wx = fx - (float)ix;
    int x0 = max(ix, 0), x1 = min(ix + 1, 6);

    for (int a = 0; a < AG; a++) {
        const float* t1 = an + ((size_t)h * AG + a) * 49;
        float v1 = bilerp7(t1, y0, y1, wy, x0, x1, wx);
        g_bias_agent[((size_t)h * AG + a) * NTOK + n] =
            v1 + ahb[((size_t)h * AG + a) * W_ + y] + awb[((size_t)h * AG + a) * W_ + x];

        const float* t2 = na + ((size_t)h * AG + a) * 49;
        float v2 = bilerp7(t2, y0, y1, wy, x0, x1, wx);
        g_bias_q[((size_t)h * NTOK + n) * AG + a] =
            v2 + hab[((size_t)h * W_ + y) * AG + a] + wab[((size_t)h * W_ + x) * AG + a];
    }
}

// ---------------- tensor-core 3xTF32 GEMM ----------------
// C(M,N) = A(M,K) * W(N,K)^T ; 128x128 CTA tile, 8 warps (4x2), warp tile 32x64.
// Split-precision: x = hi + lo (tf32 each); C += hi*hi + hi*lo + lo*hi  (~fp32 accuracy)

__device__ __forceinline__ unsigned f2tf(float x) {
    unsigned r;
    asm("cvt.rna.tf32.f32 %0, %1;" : "=r"(r) : "f"(x));
    return r;
}

__device__ __forceinline__ void mma_tf32(float c[4], const unsigned a[4], const unsigned b[2]) {
    asm volatile("mma.sync.aligned.m16n8k8.row.col.f32.tf32.tf32.f32 "
        "{%0,%1,%2,%3}, {%4,%5,%6,%7}, {%8,%9}, {%0,%1,%2,%3};\n"
        : "+f"(c[0]), "+f"(c[1]), "+f"(c[2]), "+f"(c[3])
        : "r"(a[0]), "r"(a[1]), "r"(a[2]), "r"(a[3]), "r"(b[0]), "r"(b[1]));
}

// Core compute shared by both GEMMs. A: global ptr to M-rows (row-major, ld=512).
// Wm: weight rows for this 128-col block (row-major, ld=512). Accumulates into c[2][8][4].
struct TF32Gemm {
    float c[2][8][4];

    __device__ __forceinline__ void run(const float* __restrict__ Ab,
                                        const float* __restrict__ Wm)
    {
        __shared__ __align__(16) float As[128][20];
        __shared__ __align__(16) float Bs[128][20];

        int tid = threadIdx.x;
        int lane = tid & 31;
        int wid  = tid >> 5;
        int warp_m = wid & 3;      // 0..3  (M)
        int warp_n = wid >> 2;     // 0..1  (N)
        int qr = lane >> 2;        // 0..7
        int qc = lane & 3;         // 0..3

        #pragma unroll
        for (int mi = 0; mi < 2; mi++)
            #pragma unroll
            for (int ni = 0; ni < 8; ni++)
                #pragma unroll
                for (int j = 0; j < 4; j++) c[mi][ni][j] = 0.f;

        int f0 = tid, f1 = tid + 256;        // float4 slots, 512 total per tile
        int r0 = f0 >> 2, q0 = (f0 & 3) * 4;
        int r1 = f1 >> 2, q1 = (f1 & 3) * 4;

        for (int k0 = 0; k0 < C_; k0 += 16) {
            *(float4*)&As[r0][q0] = *(const float4*)(Ab + (size_t)r0 * C_ + k0 + q0);
            *(float4*)&As[r1][q1] = *(const float4*)(Ab + (size_t)r1 * C_ + k0 + q1);
            *(float4*)&Bs[r0][q0] = *(const float4*)(Wm + (size_t)r0 * C_ + k0 + q0);
            *(float4*)&Bs[r1][q1] = *(const float4*)(Wm + (size_t)r1 * C_ + k0 + q1);
            __syncthreads();

            #pragma unroll
            for (int ks = 0; ks < 16; ks += 8) {
                // load + split B fragments (8 n-atoms)
                unsigned bh[8][2], bl[8][2];
                #pragma unroll
                for (int ni = 0; ni < 8; ni++) {
                    int n = warp_n * 64 + ni * 8 + qr;
                    float x0 = Bs[n][ks + qc];
                    float x1 = Bs[n][ks + qc + 4];
                    bh[ni][0] = f2tf(x0);
                    bh[ni][1] = f2tf(x1);
                    bl[ni][0] = f2tf(x0 - __uint_as_float(bh[ni][0]));
                    bl[ni][1] = f2tf(x1 - __uint_as_float(bh[ni][1]));
                }
                // A fragments (2 m-atoms)
                #pragma unroll
                for (int mi = 0; mi < 2; mi++) {
                    int r = warp_m * 32 + mi * 16 + qr;
                    float x0 = As[r][ks + qc];
                    float x1 = As[r + 8][ks + qc];
                    float x2 = As[r][ks + qc + 4];
                    float x3 = As[r + 8][ks + qc + 4];
                    unsigned ah[4], al[4];
                    ah[0] = f2tf(x0); ah[1] = f2tf(x1); ah[2] = f2tf(x2); ah[3] = f2tf(x3);
                    al[0] = f2tf(x0 - __uint_as_float(ah[0]));
                    al[1] = f2tf(x1 - __uint_as_float(ah[1]));
                    al[2] = f2tf(x2 - __uint_as_float(ah[2]));
                    al[3] = f2tf(x3 - __uint_as_float(ah[3]));
                    #pragma unroll
                    for (int ni = 0; ni < 8; ni++) {
                        mma_tf32(c[mi][ni], ah, bh[ni]);   // hi*hi
                        mma_tf32(c[mi][ni], ah, bl[ni]);   // hi*lo
                        mma_tf32(c[mi][ni], al, bh[ni]);   // lo*hi
                    }
                }
            }
            __syncthreads();
        }
    }
};

// K1: fused QKV (N = 1536 over q_w + kv_w)
__global__ __launch_bounds__(256) void tc_qkv(
    const float* __restrict__ A, const float* __restrict__ qw, const float* __restrict__ kvw)
{
    int bm = blockIdx.y, bn = blockIdx.x;
    int j0 = bn * 128;
    const float* Wm; float* O; int colbase;
    if (j0 < 512)        { Wm = qw  + (size_t)j0 * C_;          O = g_q; colbase = j0; }
    else if (j0 < 1024)  { Wm = kvw + (size_t)(j0 - 512) * C_;  O = g_k; colbase = j0 - 512; }
    else                 { Wm = kvw + (size_t)(j0 - 512) * C_;  O = g_v; colbase = j0 - 1024; }

    TF32Gemm g;
    g.run(A + (size_t)bm * 128 * C_, Wm);

    int lane = threadIdx.x & 31, wid = threadIdx.x >> 5;
    int warp_m = wid & 3, warp_n = wid >> 2;
    int qr = lane >> 2, qc = lane & 3;
    #pragma unroll
    for (int mi = 0; mi < 2; mi++) {
        #pragma unroll
        for (int ni = 0; ni < 8; ni++) {
            int row = bm * 128 + warp_m * 32 + mi * 16 + qr;
            int gcol = colbase + warp_n * 64 + ni * 8 + qc * 2;
            *(float2*)&O[(size_t)row * 512 + gcol]       = make_float2(g.c[mi][ni][0], g.c[mi][ni][1]);
            *(float2*)&O[(size_t)(row + 8) * 512 + gcol] = make_float2(g.c[mi][ni][2], g.c[mi][ni][3]);
        }
    }
}

// K8: projection GEMM (+bias) writing final output
__global__ __launch_bounds__(256) void tc_proj(
    const float* __restrict__ pw, const float* __restrict__ pb, float* __restrict__ out)
{
    int bm = blockIdx.y, bn = blockIdx.x;
    int colbase = bn * 128;

    TF32Gemm g;
    g.run(g_ao + (size_t)bm * 128 * C_, pw + (size_t)colbase * C_);

    int lane = threadIdx.x & 31, wid = threadIdx.x >> 5;
    int warp_m = wid & 3, warp_n = wid >> 2;
    int qr = lane >> 2, qc = lane & 3;
    #pragma unroll
    for (int mi = 0; mi < 2; mi++) {
        #pragma unroll
        for (int ni = 0; ni < 8; ni++) {
            int row = bm * 128 + warp_m * 32 + mi * 16 + qr;
            int gcol = colbase + warp_n * 64 + ni * 8 + qc * 2;
            float b0 = pb[gcol], b1 = pb[gcol + 1];
            *(float2*)&out[(size_t)row * 512 + gcol] =
                make_float2(g.c[mi][ni][0] + b0, g.c[mi][ni][1] + b1);
            *(float2*)&out[(size_t)(row + 8) * 512 + gcol] =
                make_float2(g.c[mi][ni][2] + b0, g.c[mi][ni][3] + b1);
        }
    }
}

// K2: agent token pooling: 8x8 mean over q_img (B,H,W,C) -> (B,49,C)
__global__ __launch_bounds__(256) void k_pool()
{
    int idx = blockIdx.x * 256 + threadIdx.x;   // over B_*AG*C_ = 401408
    int c = idx & 511;
    int a = (idx >> 9) % AG;
    int b = idx / (AG * C_);
    int ay = a / 7, ax = a % 7;
    float s = 0.f;
    #pragma unroll
    for (int dy = 0; dy < 8; dy++)
        for (int dx = 0; dx < 8; dx++)
            s += g_q[((size_t)(b * NTOK + (ay * 8 + dy) * W_ + ax * 8 + dx)) * C_ + c];
    g_at[idx] = s * (1.0f / 64.0f);
}

// K3: agent logits (b,h): logits[a][n] = scale*<ah_a, k_n> + bias_agent[h][a][n]
__global__ __launch_bounds__(256) void k_agent_logits()
{
    int bh = blockIdx.y;
    int b = bh >> 3, h = bh & 7;
    __shared__ __align__(16) float s_ah[AG * HD];
    for (int i = threadIdx.x; i < AG * HD; i += 256) {
        int a = i >> 6, d = i & 63;
        s_ah[i] = g_at[((size_t)b * AG + a) * C_ + h * HD + d] * 0.125f;
    }
    __syncthreads();

    int n = blockIdx.x * 256 + threadIdx.x;
    if (n >= NTOK) return;

    const float4* kp = (const float4*)(g_k + ((size_t)(b * NTOK + n)) * C_ + h * HD);
    float4 kr[16];
    #pragma unroll
    for (int i = 0; i < 16; i++) kr[i] = kp[i];

    const float4* ah4 = (const float4*)s_ah;
    for (int a = 0; a < AG; a++) {
        float acc = g_bias_agent[((size_t)h * AG + a) * NTOK + n];
        #pragma unroll
        for (int i = 0; i < 16; i++) {
            float4 av = ah4[a * 16 + i];
            acc += kr[i].x * av.x + kr[i].y * av.y + kr[i].z * av.z + kr[i].w * av.w;
        }
        g_logits[((size_t)bh * AG + a) * NTOK + n] = acc;
    }
}

// K4: softmax over n=3136 per (b,h,a) row, in-place on g_logits
__global__ __launch_bounds__(256) void k_softmax()
{
    float* row = g_logits + (size_t)blockIdx.x * NTOK;
    __shared__ float red[256];
    int t = threadIdx.x;

    float m = -1e30f;
    for (int i = t; i < NTOK; i += 256) m = fmaxf(m, row[i]);
    red[t] = m; __syncthreads();
    for (int s = 128; s > 0; s >>= 1) { if (t < s) red[t] = fmaxf(red[t], red[t + s]); __syncthreads(); }
    m = red[0]; __syncthreads();

    float sum = 0.f;
    for (int i = t; i < NTOK; i += 256) { float e = __expf(row[i] - m); row[i] = e; sum += e; }
    red[t] = sum; __syncthreads();
    for (int s = 128; s > 0; s >>= 1) { if (t < s) red[t] += red[t + s]; __syncthreads(); }
    float inv = 1.0f / red[0];

    for (int i = t; i < NTOK; i += 256) row[i] *= inv;
}

// K5: agent_v[b,h,a,d] = sum_n attn[a][n] * v[b,n,h*64+d]
__global__ __launch_bounds__(256) void k_agent_v()
{
    int bh = blockIdx.x;
    int b = bh >> 3, h = bh & 7;
    __shared__ float s_at[AG][64];
    __shared__ float s_v[64][64];
    int tid = threadIdx.x;
    int d = tid & 63;
    int as = tid >> 6;   // 0..3

    float acc[13];
    #pragma unroll
    for (int j = 0; j < 13; j++) acc[j] = 0.f;

    for (int n0 = 0; n0 < NTOK; n0 += 64) {
        for (int i = tid; i < 64 * 64; i += 256) {
            int r = i >> 6, c = i & 63;
            s_v[r][c] = g_v[((size_t)(b * NTOK + n0 + r)) * C_ + h * HD + c];
        }
        for (int i = tid; i < AG * 64; i += 256) {
            int a = i >> 6, c = i & 63;
            s_at[a][c] = g_logits[((size_t)bh * AG + a) * NTOK + n0 + c];
        }
        __syncthreads();
        for (int nn = 0; nn < 64; nn++) {
            float vv = s_v[nn][d];
            #pragma unroll
            for (int j = 0; j < 13; j++) {
                int a = as + j * 4;
                if (a < AG) acc[j] += s_at[a][nn] * vv;
            }
        }
        __syncthreads();
    }
    #pragma unroll
    for (int j = 0; j < 13; j++) {
        int a = as + j * 4;
        if (a < AG) g_av[((size_t)bh * AG + a) * HD + d] = acc[j];
    }
}

// K6: q-attention (softmax over 49 agents) fully fused per token
__global__ __launch_bounds__(128) void k_qattn()
{
    int bh = blockIdx.y;
    int b = bh >> 3, h = bh & 7;
    __shared__ __align__(16) float s_ah[AG * HD];
    __shared__ __align__(16) float s_av[AG * HD];
    for (int i = threadIdx.x; i < AG * HD; i += 128) {
        int a = i >> 6, d = i & 63;
        s_ah[i] = g_at[((size_t)b * AG + a) * C_ + h * HD + d];
        s_av[i] = g_av[((size_t)bh * AG + a) * HD + d];
    }
    __syncthreads();

    int n = blockIdx.x * 128 + threadIdx.x;
    if (n >= NTOK) return;

    const float4* qp = (const float4*)(g_q + ((size_t)(b * NTOK + n)) * C_ + h * HD);
    float4 qr[16];
    #pragma unroll
    for (int i = 0; i < 16; i++) {
        float4 t = qp[i];
        t.x *= 0.125f; t.y *= 0.125f; t.z *= 0.125f; t.w *= 0.125f;
        qr[i] = t;
    }

    const float* bq = g_bias_q + ((size_t)h * NTOK + n) * AG;
    float lg[AG];
    float m = -1e30f;
    const float4* ah4 = (const float4*)s_ah;
    for (int a = 0; a < AG; a++) {
        float acc = bq[a];
        #pragma unroll
        for (int i = 0; i < 16; i++) {
            float4 av = ah4[a * 16 + i];
            acc += qr[i].x * av.x + qr[i].y * av.y + qr[i].z * av.z + qr[i].w * av.w;
        }
        lg[a] = acc;
        m = fmaxf(m, acc);
    }
    float s = 0.f;
    for (int a = 0; a < AG; a++) { float e = __expf(lg[a] - m); lg[a] = e; s += e; }
    float inv = 1.0f / s;

    float4 o[16];
    #pragma unroll
    for (int i = 0; i < 16; i++) o[i] = make_float4(0.f, 0.f, 0.f, 0.f);
    const float4* av4 = (const float4*)s_av;
    for (int a = 0; a < AG; a++) {
        float w = lg[a] * inv;
        #pragma unroll
        for (int i = 0; i < 16; i++) {
            float4 v = av4[a * 16 + i];
            o[i].x += w * v.x; o[i].y += w * v.y; o[i].z += w * v.z; o[i].w += w * v.w;
        }
    }
    float4* op = (float4*)(g_ao + ((size_t)(b * NTOK + n)) * C_ + h * HD);
    #pragma unroll
    for (int i = 0; i < 16; i++) op[i] = o[i];
}

// K7: depthwise 3x3 conv on v (as NCHW via index math), accumulate into g_ao
__global__ __launch_bounds__(256) void k_dwc(const float* __restrict__ w, const float* __restrict__ bias)
{
    int idx = blockIdx.x * 256 + threadIdx.x;   // over MTOK*C_
    int c = idx & 511;
    int n = (idx >> 9) % NTOK;
    int b = idx / (NTOK * C_);
    int y = n / W_, x = n % W_;

    float acc = bias[c];
    #pragma unroll
    for (int dy = -1; dy <= 1; dy++) {
        int yy = y + dy;
        if (yy < 0 || yy >= H_) continue;
        #pragma unroll
        for (int dx = -1; dx <= 1; dx++) {
            int xx = x + dx;
            if (xx < 0 || xx >= W_) continue;
            acc += g_v[((size_t)(b * NTOK + yy * W_ + xx)) * C_ + c] * w[c * 9 + (dy + 1) * 3 + (dx + 1)];
        }
    }
    g_ao[idx] += acc;
}

// ---------------- launch ----------------
extern "C" void kernel_launch(void* const* d_in, const int* in_sizes, int n_in,
                              void* d_out, int out_size)
{
    int base = (n_in >= 15 && in_sizes[1] == 1) ? 3 : 1;

    const float* x      = (const float*)d_in[0];
    const float* q_w    = (const float*)d_in[base + 0];
    const float* kv_w   = (const float*)d_in[base + 1];
    const float* proj_w = (const float*)d_in[base + 2];
    const float* proj_b = (const float*)d_in[base + 3];
    const float* dwc_w  = (const float*)d_in[base + 4];
    const float* dwc_b  = (const float*)d_in[base + 5];
    const float* an_b   = (const float*)d_in[base + 6];
    const float* na_b   = (const float*)d_in[base + 7];
    const float* ah_b   = (const float*)d_in[base + 8];
    const float* aw_b   = (const float*)d_in[base + 9];
    const float* ha_b   = (const float*)d_in[base + 10];
    const float* wa_b   = (const float*)d_in[base + 11];
    float* out = (float*)d_out;

    k_bias<<<98, 256>>>(an_b, na_b, ah_b, aw_b, ha_b, wa_b);
    tc_qkv<<<dim3(12, MTOK / 128), 256>>>(x, q_w, kv_w);
    k_pool<<<(B_ * AG * C_) / 256, 256>>>();
    k_agent_logits<<<dim3((NTOK + 255) / 256, B_ * HEADS), 256>>>();
    k_softmax<<<B_ * HEADS * AG, 256>>>();
    k_agent_v<<<B_ * HEADS, 256>>>();
    k_qattn<<<dim3((NTOK + 127) / 128, B_ * HEADS), 128>>>();
    k_dwc<<<(MTOK * C_) / 256, 256>>>(dwc_w, dwc_b);
    tc_proj<<<dim3(4, MTOK / 128), 256>>>(proj_w, proj_b, out);
}

// round 6
// speedup vs baseline: 1.5103x; 1.2454x over previous
#include <cuda_runtime.h>
#include <cuda_bf16.h>
#include <cstdint>
#include <math.h>

// ---------------- problem constants ----------------
constexpr int B_    = 16;
constexpr int C_    = 512;
constexpr int H_    = 56;
constexpr int W_    = 56;
constexpr int NTOK  = H_ * W_;        // 3136
constexpr int MTOK  = B_ * NTOK;      // 50176
constexpr int HEADS = 8;
constexpr int HD    = 64;
constexpr int AG    = 49;             // agent tokens

// ---------------- scratch (device globals: allocation-free) ----------------
__device__ float g_q [MTOK * C_];
__device__ float g_k [MTOK * C_];
__device__ float g_v [MTOK * C_];
__device__ float g_ao[MTOK * C_];                  // attention output + dwc (pre-proj)
__device__ float g_logits[B_ * HEADS * AG * NTOK]; // agent attn logits / probs
__device__ float g_at[B_ * AG * C_];               // agent tokens
__device__ float g_av[B_ * HEADS * AG * HD];       // agent_v
__device__ float g_bias_agent[HEADS * AG * NTOK];  // pb1 + pb2  [h][a][n]
__device__ float g_bias_q    [HEADS * NTOK * AG];  // ab1 + ab2  [h][n][a]

// bf16 split buffers (hi/lo) for tensor-core GEMMs
__device__ __nv_bfloat16 g_ahi[MTOK * C_];
__device__ __nv_bfloat16 g_alo[MTOK * C_];
__device__ __nv_bfloat16 g_whi[2048 * C_];   // rows: 0-511 q_w, 512-1535 kv_w, 1536-2047 proj_w
__device__ __nv_bfloat16 g_wlo[2048 * C_];

// ---------------- mma / ldmatrix helpers (legacy path, sm_103-safe) ----------------
__device__ __forceinline__ uint32_t smem_u32(const void* p) {
    uint32_t a;
    asm("{ .reg .u64 t; cvta.to.shared.u64 t, %1; cvt.u32.u64 %0, t; }" : "=r"(a) : "l"(p));
    return a;
}
#define LDSM_X4(r, addr) \
    asm volatile("ldmatrix.sync.aligned.m8n8.x4.shared.b16 {%0,%1,%2,%3}, [%4];" \
        : "=r"((r)[0]), "=r"((r)[1]), "=r"((r)[2]), "=r"((r)[3]) : "r"(addr))

__device__ __forceinline__ void mma_bf16(float c[4], const uint32_t a[4], const uint32_t b[2]) {
    asm volatile("mma.sync.aligned.m16n8k16.row.col.f32.bf16.bf16.f32 "
        "{%0,%1,%2,%3}, {%4,%5,%6,%7}, {%8,%9}, {%0,%1,%2,%3};"
        : "+f"(c[0]), "+f"(c[1]), "+f"(c[2]), "+f"(c[3])
        : "r"(a[0]), "r"(a[1]), "r"(a[2]), "r"(a[3]), "r"(b[0]), "r"(b[1]));
}
#define CP_ASYNC16(dst, src) \
    asm volatile("cp.async.cg.shared.global [%0], [%1], 16;" :: "r"(dst), "l"(src))
#define CP_COMMIT() asm volatile("cp.async.commit_group;")

// ---------------- split kernels: fp32 -> bf16 hi + bf16 lo ----------------
__global__ __launch_bounds__(256) void k_split_x(const float* __restrict__ src) {
    size_t i = (size_t)blockIdx.x * 256 + threadIdx.x;
    float v = src[i];
    __nv_bfloat16 hi = __float2bfloat16(v);
    g_ahi[i] = hi;
    g_alo[i] = __float2bfloat16(v - __bfloat162float(hi));
}
__global__ __launch_bounds__(256) void k_split_ao() {
    size_t i = (size_t)blockIdx.x * 256 + threadIdx.x;
    float v = g_ao[i];
    __nv_bfloat16 hi = __float2bfloat16(v);
    g_ahi[i] = hi;
    g_alo[i] = __float2bfloat16(v - __bfloat162float(hi));
}
__global__ __launch_bounds__(256) void k_split_w(const float* __restrict__ qw,
                                                 const float* __restrict__ kvw,
                                                 const float* __restrict__ pw) {
    size_t i = (size_t)blockIdx.x * 256 + threadIdx.x;   // over 2048*512
    size_t row = i >> 9;
    float v;
    if (row < 512)        v = qw[i];
    else if (row < 1536)  v = kvw[i - (size_t)512 * 512];
    else                  v = pw[i - (size_t)1536 * 512];
    __nv_bfloat16 hi = __float2bfloat16(v);
    g_whi[i] = hi;
    g_wlo[i] = __float2bfloat16(v - __bfloat162float(hi));
}

// ---------------- bf16 split GEMM: C(M,N) = A(M,512) * W(N,512)^T ----------------
// CTA 128x128, 8 warps (4x2, warp tile 32x64), K chunks of 32, 2-stage cp.async pipe.
// 3-term split: hh + hl + lh via mma.m16n8k16.bf16.
constexpr int T_ROWB = 80;                       // 32 bf16 + 16B pad per row
constexpr int TILE_B = 128 * T_ROWB;             // 10240 B
constexpr int STAGE_B = 4 * TILE_B;              // AHI, ALO, BHI, BLO
constexpr int GEMM_SMEM = 2 * STAGE_B;           // 81920 B

template <bool PROJ>
__global__ __launch_bounds__(256) void bf_gemm(const float* __restrict__ pb,
                                               float* __restrict__ out)
{
    extern __shared__ char smem[];
    const uint32_t sb = smem_u32(smem);
    const int tid = threadIdx.x;
    const int lane = tid & 31, wid = tid >> 5;
    const int warp_m = wid & 3, warp_n = wid >> 2;
    const int bm = blockIdx.y, bn = blockIdx.x;
    const int j0 = bn * 128;
    const int wrow0 = (PROJ ? 1536 : 0) + j0;
    const size_t arow0 = (size_t)bm * 128;

    float acc[2][8][4] = {};

    auto load_chunk = [&](int chunk, int stage) {
        const int k0 = chunk * 32;
        const uint32_t dstb = sb + stage * STAGE_B;
        #pragma unroll
        for (int i = 0; i < 8; i++) {
            int u = i * 256 + tid;
            int t = u >> 9;             // tile id 0..3
            int s = u & 511;
            int r = s >> 2;             // row 0..127
            int c = s & 3;              // 16B segment
            uint32_t dst = dstb + t * TILE_B + r * T_ROWB + c * 16;
            const __nv_bfloat16* src;
            if (t == 0)      src = g_ahi + (arow0 + r) * C_ + k0 + c * 8;
            else if (t == 1) src = g_alo + (arow0 + r) * C_ + k0 + c * 8;
            else if (t == 2) src = g_whi + (size_t)(wrow0 + r) * C_ + k0 + c * 8;
            else             src = g_wlo + (size_t)(wrow0 + r) * C_ + k0 + c * 8;
            CP_ASYNC16(dst, src);
        }
        CP_COMMIT();
    };

    load_chunk(0, 0);

    for (int ch = 0; ch < 16; ch++) {
        if (ch + 1 < 16) {
            load_chunk(ch + 1, (ch + 1) & 1);
            asm volatile("cp.async.wait_group 1;");
        } else {
            asm volatile("cp.async.wait_group 0;");
        }
        __syncthreads();

        const uint32_t stb = sb + (ch & 1) * STAGE_B;
        const uint32_t ahb = stb;
        const uint32_t alb = stb + TILE_B;
        const uint32_t bhb = stb + 2 * TILE_B;
        const uint32_t blb = stb + 3 * TILE_B;

        #pragma unroll
        for (int kk = 0; kk < 32; kk += 16) {
            uint32_t AH[2][4], AL[2][4], BH[4][4], BL[4][4];
            // A: lanes 0-15 -> rows 0-15 (k low 8), lanes 16-31 -> rows 0-15 (k high 8)
            int ar = warp_m * 32 + (lane & 15);
            int acb = (kk + ((lane >> 4) << 3)) * 2;
            #pragma unroll
            for (int mi = 0; mi < 2; mi++) {
                LDSM_X4(AH[mi], ahb + (ar + mi * 16) * T_ROWB + acb);
                LDSM_X4(AL[mi], alb + (ar + mi * 16) * T_ROWB + acb);
            }
            // B: x4 covers 2 n-atoms: m0=(n0-7,klo) m1=(n0-7,khi) m2=(n8-15,klo) m3=(n8-15,khi)
            int br = warp_n * 64 + (lane & 7) + ((lane >> 4) << 3);
            int bcb = (kk + (((lane >> 3) & 1) << 3)) * 2;
            #pragma unroll
            for (int pi = 0; pi < 4; pi++) {
                LDSM_X4(BH[pi], bhb + (br + pi * 16) * T_ROWB + bcb);
                LDSM_X4(BL[pi], blb + (br + pi * 16) * T_ROWB + bcb);
            }
            #pragma unroll
            for (int mi = 0; mi < 2; mi++)
                #pragma unroll
                for (int ni = 0; ni < 8; ni++) {
                    const uint32_t* bh2 = &BH[ni >> 1][(ni & 1) * 2];
                    const uint32_t* bl2 = &BL[ni >> 1][(ni & 1) * 2];
                    mma_bf16(acc[mi][ni], AH[mi], bh2);   // hi*hi
                    mma_bf16(acc[mi][ni], AH[mi], bl2);   // hi*lo
                    mma_bf16(acc[mi][ni], AL[mi], bh2);   // lo*hi
                }
        }
        __syncthreads();
    }

    // epilogue
    {
        int qr = lane >> 2, qc = lane & 3;
        float* O; int colbase;
        if (PROJ) { O = out; colbase = j0; }
        else {
            if (j0 < 512)        { O = g_q; colbase = j0; }
            else if (j0 < 1024)  { O = g_k; colbase = j0 - 512; }
            else                 { O = g_v; colbase = j0 - 1024; }
        }
        #pragma unroll
        for (int mi = 0; mi < 2; mi++) {
            #pragma unroll
            for (int ni = 0; ni < 8; ni++) {
                int row = bm * 128 + warp_m * 32 + mi * 16 + qr;
                int gcol = colbase + warp_n * 64 + ni * 8 + qc * 2;
                float b0 = 0.f, b1 = 0.f;
                if (PROJ) { b0 = pb[gcol]; b1 = pb[gcol + 1]; }
                *(float2*)&O[(size_t)row * 512 + gcol] =
                    make_float2(acc[mi][ni][0] + b0, acc[mi][ni][1] + b1);
                *(float2*)&O[(size_t)(row + 8) * 512 + gcol] =
                    make_float2(acc[mi][ni][2] + b0, acc[mi][ni][3] + b1);
            }
        }
    }
}

// ---------------- bilinear (jax.image.resize 7 -> 56, clamp-edge) ----------------
__device__ __forceinline__ float bilerp7(const float* t, int y0, int y1, float wy,
                                         int x0, int x1, float wx) {
    float v00 = t[y0 * 7 + x0], v01 = t[y0 * 7 + x1];
    float v10 = t[y1 * 7 + x0], v11 = t[y1 * 7 + x1];
    float a = v00 + (v01 - v00) * wx;
    float b = v10 + (v11 - v10) * wx;
    return a + (b - a) * wy;
}

// K0: precompute both positional-bias tables
__global__ __launch_bounds__(256) void k_bias(
    const float* __restrict__ an, const float* __restrict__ na,
    const float* __restrict__ ahb, const float* __restrict__ awb,
    const float* __restrict__ hab, const float* __restrict__ wab)
{
    int idx = blockIdx.x * 256 + threadIdx.x;          // over HEADS*NTOK = 25088
    if (idx >= HEADS * NTOK) return;
    int h = idx / NTOK;
    int n = idx % NTOK;
    int y = n / W_, x = n % W_;

    float fy = (y + 0.5f) * 0.125f - 0.5f;
    int iy = (int)floorf(fy);
    float wy = fy - (float)iy;
    int y0 = max(iy, 0), y1 = min(iy + 1, 6);

    float fx = (x + 0.5f) * 0.125f - 0.5f;
    int ix = (int)floorf(fx);
    float wx = fx - (float)ix;
    int x0 = max(ix, 0), x1 = min(ix + 1, 6);

    for (int a = 0; a < AG; a++) {
        const float* t1 = an + ((size_t)h * AG + a) * 49;
        float v1 = bilerp7(t1, y0, y1, wy, x0, x1, wx);
        g_bias_agent[((size_t)h * AG + a) * NTOK + n] =
            v1 + ahb[((size_t)h * AG + a) * W_ + y] + awb[((size_t)h * AG + a) * W_ + x];

        const float* t2 = na + ((size_t)h * AG + a) * 49;
        float v2 = bilerp7(t2, y0, y1, wy, x0, x1, wx);
        g_bias_q[((size_t)h * NTOK + n) * AG + a] =
            v2 + hab[((size_t)h * W_ + y) * AG + a] + wab[((size_t)h * W_ + x) * AG + a];
    }
}

// K2: agent token pooling: 8x8 mean over q_img (B,H,W,C) -> (B,49,C)
__global__ __launch_bounds__(256) void k_pool()
{
    int idx = blockIdx.x * 256 + threadIdx.x;   // over B_*AG*C_ = 401408
    int c = idx & 511;
    int a = (idx >> 9) % AG;
    int b = idx / (AG * C_);
    int ay = a / 7, ax = a % 7;
    float s = 0.f;
    #pragma unroll
    for (int dy = 0; dy < 8; dy++)
        for (int dx = 0; dx < 8; dx++)
            s += g_q[((size_t)(b * NTOK + (ay * 8 + dy) * W_ + ax * 8 + dx)) * C_ + c];
    g_at[idx] = s * (1.0f / 64.0f);
}

// K3: agent logits (b,h): logits[a][n] = scale*<ah_a, k_n> + bias_agent[h][a][n]
__global__ __launch_bounds__(256) void k_agent_logits()
{
    int bh = blockIdx.y;
    int b = bh >> 3, h = bh & 7;
    __shared__ __align__(16) float s_ah[AG * HD];
    for (int i = threadIdx.x; i < AG * HD; i += 256) {
        int a = i >> 6, d = i & 63;
        s_ah[i] = g_at[((size_t)b * AG + a) * C_ + h * HD + d] * 0.125f;
    }
    __syncthreads();

    int n = blockIdx.x * 256 + threadIdx.x;
    if (n >= NTOK) return;

    const float4* kp = (const float4*)(g_k + ((size_t)(b * NTOK + n)) * C_ + h * HD);
    float4 kr[16];
    #pragma unroll
    for (int i = 0; i < 16; i++) kr[i] = kp[i];

    const float4* ah4 = (const float4*)s_ah;
    for (int a = 0; a < AG; a++) {
        float acc = g_bias_agent[((size_t)h * AG + a) * NTOK + n];
        #pragma unroll
        for (int i = 0; i < 16; i++) {
            float4 av = ah4[a * 16 + i];
            acc += kr[i].x * av.x + kr[i].y * av.y + kr[i].z * av.z + kr[i].w * av.w;
        }
        g_logits[((size_t)bh * AG + a) * NTOK + n] = acc;
    }
}

// K4: softmax over n=3136 per (b,h,a) row, in-place on g_logits
__global__ __launch_bounds__(256) void k_softmax()
{
    float* row = g_logits + (size_t)blockIdx.x * NTOK;
    __shared__ float red[256];
    int t = threadIdx.x;

    float m = -1e30f;
    for (int i = t; i < NTOK; i += 256) m = fmaxf(m, row[i]);
    red[t] = m; __syncthreads();
    for (int s = 128; s > 0; s >>= 1) { if (t < s) red[t] = fmaxf(red[t], red[t + s]); __syncthreads(); }
    m = red[0]; __syncthreads();

    float sum = 0.f;
    for (int i = t; i < NTOK; i += 256) { float e = __expf(row[i] - m); row[i] = e; sum += e; }
    red[t] = sum; __syncthreads();
    for (int s = 128; s > 0; s >>= 1) { if (t < s) red[t] += red[t + s]; __syncthreads(); }
    float inv = 1.0f / red[0];

    for (int i = t; i < NTOK; i += 256) row[i] *= inv;
}

// K5: agent_v[b,h,a,d] = sum_n attn[a][n] * v[b,n,h*64+d]
__global__ __launch_bounds__(256) void k_agent_v()
{
    int bh = blockIdx.x;
    int b = bh >> 3, h = bh & 7;
    __shared__ float s_at[AG][64];
    __shared__ float s_v[64][64];
    int tid = threadIdx.x;
    int d = tid & 63;
    int as = tid >> 6;   // 0..3

    float acc[13];
    #pragma unroll
    for (int j = 0; j < 13; j++) acc[j] = 0.f;

    for (int n0 = 0; n0 < NTOK; n0 += 64) {
        for (int i = tid; i < 64 * 64; i += 256) {
            int r = i >> 6, c = i & 63;
            s_v[r][c] = g_v[((size_t)(b * NTOK + n0 + r)) * C_ + h * HD + c];
        }
        for (int i = tid; i < AG * 64; i += 256) {
            int a = i >> 6, c = i & 63;
            s_at[a][c] = g_logits[((size_t)bh * AG + a) * NTOK + n0 + c];
        }
        __syncthreads();
        for (int nn = 0; nn < 64; nn++) {
            float vv = s_v[nn][d];
            #pragma unroll
            for (int j = 0; j < 13; j++) {
                int a = as + j * 4;
                if (a < AG) acc[j] += s_at[a][nn] * vv;
            }
        }
        __syncthreads();
    }
    #pragma unroll
    for (int j = 0; j < 13; j++) {
        int a = as + j * 4;
        if (a < AG) g_av[((size_t)bh * AG + a) * HD + d] = acc[j];
    }
}

// K6: q-attention (softmax over 49 agents) + fused depthwise 3x3 conv on v
__global__ __launch_bounds__(128) void k_qattn(const float* __restrict__ dwc_w,
                                               const float* __restrict__ dwc_b)
{
    int bh = blockIdx.y;
    int b = bh >> 3, h = bh & 7;
    __shared__ __align__(16) float s_ah[AG * HD];
    __shared__ __align__(16) float s_av[AG * HD];
    __shared__ __align__(16) float s_w[9][64];   // dwc weights for this head's 64 channels
    __shared__ __align__(16) float s_b[64];
    for (int i = threadIdx.x; i < AG * HD; i += 128) {
        int a = i >> 6, d = i & 63;
        s_ah[i] = g_at[((size_t)b * AG + a) * C_ + h * HD + d];
        s_av[i] = g_av[((size_t)bh * AG + a) * HD + d];
    }
    for (int i = threadIdx.x; i < 9 * 64; i += 128) {
        int j = i / 64, ci = i % 64;
        s_w[j][ci] = dwc_w[(size_t)(h * 64 + ci) * 9 + j];
    }
    if (threadIdx.x < 64) s_b[threadIdx.x] = dwc_b[h * 64 + threadIdx.x];
    __syncthreads();

    int n = blockIdx.x * 128 + threadIdx.x;
    if (n >= NTOK) return;

    const float4* qp = (const float4*)(g_q + ((size_t)(b * NTOK + n)) * C_ + h * HD);
    float4 qr[16];
    #pragma unroll
    for (int i = 0; i < 16; i++) {
        float4 t = qp[i];
        t.x *= 0.125f; t.y *= 0.125f; t.z *= 0.125f; t.w *= 0.125f;
        qr[i] = t;
    }

    const float* bq = g_bias_q + ((size_t)h * NTOK + n) * AG;
    float lg[AG];
    float m = -1e30f;
    const float4* ah4 = (const float4*)s_ah;
    for (int a = 0; a < AG; a++) {
        float acc = bq[a];
        #pragma unroll
        for (int i = 0; i < 16; i++) {
            float4 av = ah4[a * 16 + i];
            acc += qr[i].x * av.x + qr[i].y * av.y + qr[i].z * av.z + qr[i].w * av.w;
        }
        lg[a] = acc;
        m = fmaxf(m, acc);
    }
    float s = 0.f;
    for (int a = 0; a < AG; a++) { float e = __expf(lg[a] - m); lg[a] = e; s += e; }
    float inv = 1.0f / s;

    float4 o[16];
    #pragma unroll
    for (int i = 0; i < 16; i++) o[i] = make_float4(0.f, 0.f, 0.f, 0.f);
    const float4* av4 = (const float4*)s_av;
    for (int a = 0; a < AG; a++) {
        float w = lg[a] * inv;
        #pragma unroll
        for (int i = 0; i < 16; i++) {
            float4 v = av4[a * 16 + i];
            o[i].x += w * v.x; o[i].y += w * v.y; o[i].z += w * v.z; o[i].w += w * v.w;
        }
    }

    // fused depthwise 3x3 conv on v for channels [h*64, h*64+64)
    int y = n / W_, x = n % W_;
    const float4* wb4 = (const float4*)s_b;
    #pragma unroll
    for (int i = 0; i < 16; i++) {
        float4 bb = wb4[i];
        o[i].x += bb.x; o[i].y += bb.y; o[i].z += bb.z; o[i].w += bb.w;
    }
    #pragma unroll
    for (int dy = -1; dy <= 1; dy++) {
        int yy = y + dy;
        if (yy < 0 || yy >= H_) continue;
        #pragma unroll
        for (int dx = -1; dx <= 1; dx++) {
            int xx = x + dx;
            if (xx < 0 || xx >= W_) continue;
            int j = (dy + 1) * 3 + (dx + 1);
            const float4* vp = (const float4*)(g_v + ((size_t)(b * NTOK + yy * W_ + xx)) * C_ + h * HD);
            const float4* wj = (const float4*)&s_w[j][0];
            #pragma unroll
            for (int i = 0; i < 16; i++) {
                float4 v = vp[i];
                float4 w = wj[i];
                o[i].x += v.x * w.x; o[i].y += v.y * w.y;
                o[i].z += v.z * w.z; o[i].w += v.w * w.w;
            }
        }
    }

    float4* op = (float4*)(g_ao + ((size_t)(b * NTOK + n)) * C_ + h * HD);
    #pragma unroll
    for (int i = 0; i < 16; i++) op[i] = o[i];
}

// ---------------- launch ----------------
extern "C" void kernel_launch(void* const* d_in, const int* in_sizes, int n_in,
                              void* d_out, int out_size)
{
    int base = (n_in >= 15 && in_sizes[1] == 1) ? 3 : 1;

    const float* x      = (const float*)d_in[0];
    const float* q_w    = (const float*)d_in[base + 0];
    const float* kv_w   = (const float*)d_in[base + 1];
    const float* proj_w = (const float*)d_in[base + 2];
    const float* proj_b = (const float*)d_in[base + 3];
    const float* dwc_w  = (const float*)d_in[base + 4];
    const float* dwc_b  = (const float*)d_in[base + 5];
    const float* an_b   = (const float*)d_in[base + 6];
    const float* na_b   = (const float*)d_in[base + 7];
    const float* ah_b   = (const float*)d_in[base + 8];
    const float* aw_b   = (const float*)d_in[base + 9];
    const float* ha_b   = (const float*)d_in[base + 10];
    const float* wa_b   = (const float*)d_in[base + 11];
    float* out = (float*)d_out;

    static bool attr_done = false;
    if (!attr_done) {
        cudaFuncSetAttribute(bf_gemm<false>, cudaFuncAttributeMaxDynamicSharedMemorySize, GEMM_SMEM);
        cudaFuncSetAttribute(bf_gemm<true>,  cudaFuncAttributeMaxDynamicSharedMemorySize, GEMM_SMEM);
        attr_done = true;
    }

    k_bias<<<98, 256>>>(an_b, na_b, ah_b, aw_b, ha_b, wa_b);
    k_split_w<<<(2048 * C_) / 256, 256>>>(q_w, kv_w, proj_w);
    k_split_x<<<(int)(((size_t)MTOK * C_) / 256), 256>>>(x);
    bf_gemm<false><<<dim3(12, MTOK / 128), 256, GEMM_SMEM>>>(nullptr, nullptr);
    k_pool<<<(B_ * AG * C_) / 256, 256>>>();
    k_agent_logits<<<dim3((NTOK + 255) / 256, B_ * HEADS), 256>>>();
    k_softmax<<<B_ * HEADS * AG, 256>>>();
    k_agent_v<<<B_ * HEADS, 256>>>();
    k_qattn<<<dim3((NTOK + 127) / 128, B_ * HEADS), 128>>>(dwc_w, dwc_b);
    k_split_ao<<<(int)(((size_t)MTOK * C_) / 256), 256>>>();
    bf_gemm<true><<<dim3(4, MTOK / 128), 256, GEMM_SMEM>>>(proj_b, out);
}

// round 8
// speedup vs baseline: 2.3015x; 1.5239x over previous
#include <cuda_runtime.h>
#include <cuda_fp16.h>
#include <cuda_bf16.h>
#include <cstdint>
#include <math.h>

// ---------------- problem constants ----------------
constexpr int B_    = 16;
constexpr int C_    = 512;
constexpr int H_    = 56;
constexpr int W_    = 56;
constexpr int NTOK  = H_ * W_;        // 3136
constexpr int MTOK  = B_ * NTOK;      // 50176
constexpr int HEADS = 8;
constexpr int HD    = 64;
constexpr int AG    = 49;             // agent tokens

// ---------------- scratch (device globals: allocation-free) ----------------
__device__ float g_q [MTOK * C_];
__device__ float g_k [MTOK * C_];
__device__ float g_v [MTOK * C_];
__device__ float g_logits[B_ * HEADS * AG * NTOK]; // agent attn logits / probs
__device__ float g_at[B_ * AG * C_];               // agent tokens
__device__ float g_av[B_ * HEADS * AG * HD];       // agent_v
__device__ float g_bias_agent[HEADS * AG * NTOK];  // pb1 + pb2  [h][a][n]
__device__ float g_bias_q    [HEADS * NTOK * AG];  // ab1 + ab2  [h][n][a]

// fp16 GEMM operand buffers
__device__ __half g_xh[MTOK * C_];    // A matrix: x (for qkv), then attn+dwc output (for proj)
__device__ __half g_wh[2048 * C_];    // rows: 0-511 q_w, 512-1535 kv_w, 1536-2047 proj_w

// ---------------- helpers ----------------
__device__ __forceinline__ uint32_t h2_as_u32(__half2 h) {
    union { __half2 h; uint32_t u; } cvt;
    cvt.h = h;
    return cvt.u;
}
__device__ __forceinline__ uint32_t pack_half2(float a, float b) {
    return h2_as_u32(__floats2half2_rn(a, b));
}
__device__ __forceinline__ uint32_t smem_u32(const void* p) {
    uint32_t a;
    asm("{ .reg .u64 t; cvta.to.shared.u64 t, %1; cvt.u32.u64 %0, t; }" : "=r"(a) : "l"(p));
    return a;
}
#define LDSM_X4(r, addr) \
    asm volatile("ldmatrix.sync.aligned.m8n8.x4.shared.b16 {%0,%1,%2,%3}, [%4];" \
        : "=r"((r)[0]), "=r"((r)[1]), "=r"((r)[2]), "=r"((r)[3]) : "r"(addr))

__device__ __forceinline__ void mma_f16(float c[4], const uint32_t a[4], const uint32_t b[2]) {
    asm volatile("mma.sync.aligned.m16n8k16.row.col.f32.f16.f16.f32 "
        "{%0,%1,%2,%3}, {%4,%5,%6,%7}, {%8,%9}, {%0,%1,%2,%3};"
        : "+f"(c[0]), "+f"(c[1]), "+f"(c[2]), "+f"(c[3])
        : "r"(a[0]), "r"(a[1]), "r"(a[2]), "r"(a[3]), "r"(b[0]), "r"(b[1]));
}
#define CP_ASYNC16(dst, src) \
    asm volatile("cp.async.cg.shared.global [%0], [%1], 16;" :: "r"(dst), "l"(src))
#define CP_COMMIT() asm volatile("cp.async.commit_group;")

// ---------------- convert kernels: fp32 -> fp16 ----------------
__global__ __launch_bounds__(256) void k_half_x(const float* __restrict__ src) {
    size_t i = ((size_t)blockIdx.x * 256 + threadIdx.x) * 4;
    float4 v = *(const float4*)(src + i);
    uint2 u;
    u.x = pack_half2(v.x, v.y);
    u.y = pack_half2(v.z, v.w);
    *(uint2*)(g_xh + i) = u;
}
__global__ __launch_bounds__(256) void k_half_w(const float* __restrict__ qw,
                                                const float* __restrict__ kvw,
                                                const float* __restrict__ pw) {
    size_t i = ((size_t)blockIdx.x * 256 + threadIdx.x) * 4;   // over 2048*512
    size_t row = i >> 9;
    const float* src;
    if (row < 512)        src = qw + i;
    else if (row < 1536)  src = kvw + (i - (size_t)512 * 512);
    else                  src = pw + (i - (size_t)1536 * 512);
    float4 v = *(const float4*)src;
    uint2 u;
    u.x = pack_half2(v.x, v.y);
    u.y = pack_half2(v.z, v.w);
    *(uint2*)(g_wh + i) = u;
}

// ---------------- fp16 GEMM: C(M,N) = A(M,512) * W(N,512)^T ----------------
// CTA 128x128, 8 warps (4x2, warp tile 32x64), K chunks of 32, 3-stage cp.async pipe.
constexpr int T_ROWB = 80;                       // 32 fp16 (64B) + 16B pad per row
constexpr int TILE_B = 128 * T_ROWB;             // 10240 B
constexpr int STAGE_B = 2 * TILE_B;              // A, B
constexpr int NSTAGE = 3;
constexpr int GEMM_SMEM = NSTAGE * STAGE_B;      // 61440 B

template <bool PROJ>
__global__ __launch_bounds__(256) void hf_gemm(const float* __restrict__ pb,
                                               float* __restrict__ out)
{
    extern __shared__ char smem[];
    const uint32_t sb = smem_u32(smem);
    const int tid = threadIdx.x;
    const int lane = tid & 31, wid = tid >> 5;
    const int warp_m = wid & 3, warp_n = wid >> 2;
    const int bm = blockIdx.y, bn = blockIdx.x;
    const int j0 = bn * 128;
    const int wrow0 = (PROJ ? 1536 : 0) + j0;
    const size_t arow0 = (size_t)bm * 128;

    float acc[2][8][4] = {};

    auto load_chunk = [&](int chunk, int stage) {
        const int k0 = chunk * 32;
        const uint32_t dstb = sb + stage * STAGE_B;
        #pragma unroll
        for (int i = 0; i < 4; i++) {
            int u = i * 256 + tid;      // 0..1023
            int t = u >> 9;             // 0 = A, 1 = B
            int s = u & 511;
            int r = s >> 2;             // row 0..127
            int c = s & 3;              // 16B segment
            uint32_t dst = dstb + t * TILE_B + r * T_ROWB + c * 16;
            const __half* src = (t == 0)
                ? g_xh + (arow0 + r) * C_ + k0 + c * 8
                : g_wh + (size_t)(wrow0 + r) * C_ + k0 + c * 8;
            CP_ASYNC16(dst, src);
        }
        CP_COMMIT();
    };

    load_chunk(0, 0);
    load_chunk(1, 1);

    for (int ch = 0; ch < 16; ch++) {
        asm volatile("cp.async.wait_group 1;");
        __syncthreads();
        if (ch + 2 < 16) load_chunk(ch + 2, (ch + 2) % NSTAGE);

        const uint32_t stb = sb + (ch % NSTAGE) * STAGE_B;
        const uint32_t ahb = stb;
        const uint32_t bhb = stb + TILE_B;

        #pragma unroll
        for (int kk = 0; kk < 32; kk += 16) {
            uint32_t AH[2][4], BH[4][4];
            // A: lanes 0-15 -> rows (k low 8), lanes 16-31 -> (k high 8)
            int ar = warp_m * 32 + (lane & 15);
            int acb = (kk + ((lane >> 4) << 3)) * 2;
            #pragma unroll
            for (int mi = 0; mi < 2; mi++)
                LDSM_X4(AH[mi], ahb + (ar + mi * 16) * T_ROWB + acb);
            // B: x4 covers 2 n-atoms
            int br = warp_n * 64 + (lane & 7) + ((lane >> 4) << 3);
            int bcb = (kk + (((lane >> 3) & 1) << 3)) * 2;
            #pragma unroll
            for (int pi = 0; pi < 4; pi++)
                LDSM_X4(BH[pi], bhb + (br + pi * 16) * T_ROWB + bcb);

            #pragma unroll
            for (int mi = 0; mi < 2; mi++)
                #pragma unroll
                for (int ni = 0; ni < 8; ni++)
                    mma_f16(acc[mi][ni], AH[mi], &BH[ni >> 1][(ni & 1) * 2]);
        }
        __syncthreads();
    }

    // epilogue
    {
        int qr = lane >> 2, qc = lane & 3;
        float* O; int colbase;
        if (PROJ) { O = out; colbase = j0; }
        else {
            if (j0 < 512)        { O = g_q; colbase = j0; }
            else if (j0 < 1024)  { O = g_k; colbase = j0 - 512; }
            else                 { O = g_v; colbase = j0 - 1024; }
        }
        #pragma unroll
        for (int mi = 0; mi < 2; mi++) {
            #pragma unroll
            for (int ni = 0; ni < 8; ni++) {
                int row = bm * 128 + warp_m * 32 + mi * 16 + qr;
                int gcol = colbase + warp_n * 64 + ni * 8 + qc * 2;
                float b0 = 0.f, b1 = 0.f;
                if (PROJ) { b0 = pb[gcol]; b1 = pb[gcol + 1]; }
                *(float2*)&O[(size_t)row * 512 + gcol] =
                    make_float2(acc[mi][ni][0] + b0, acc[mi][ni][1] + b1);
                *(float2*)&O[(size_t)(row + 8) * 512 + gcol] =
                    make_float2(acc[mi][ni][2] + b0, acc[mi][ni][3] + b1);
            }
        }
    }
}

// ---------------- bilinear (jax.image.resize 7 -> 56, clamp-edge) ----------------
__device__ __forceinline__ float bilerp7(const float* t, int y0, int y1, float wy,
                                         int x0, int x1, float wx) {
    float v00 = t[y0 * 7 + x0], v01 = t[y0 * 7 + x1];
    float v10 = t[y1 * 7 + x0], v11 = t[y1 * 7 + x1];
    float a = v00 + (v01 - v00) * wx;
    float b = v10 + (v11 - v10) * wx;
    return a + (b - a) * wy;
}

// K0: precompute both positional-bias tables
__global__ __launch_bounds__(256) void k_bias(
    const float* __restrict__ an, const float* __restrict__ na,
    const float* __restrict__ ahb, const float* __restrict__ awb,
    const float* __restrict__ hab, const float* __restrict__ wab)
{
    int idx = blockIdx.x * 256 + threadIdx.x;          // over HEADS*NTOK = 25088
    if (idx >= HEADS * NTOK) return;
    int h = idx / NTOK;
    int n = idx % NTOK;
    int y = n / W_, x = n % W_;

    float fy = (y + 0.5f) * 0.125f - 0.5f;
    int iy = (int)floorf(fy);
    float wy = fy - (float)iy;
    int y0 = max(iy, 0), y1 = min(iy + 1, 6);

    float fx = (x + 0.5f) * 0.125f - 0.5f;
    int ix = (int)floorf(fx);
    float wx = fx - (float)ix;
    int x0 = max(ix, 0), x1 = min(ix + 1, 6);

    for (int a = 0; a < AG; a++) {
        const float* t1 = an + ((size_t)h * AG + a) * 49;
        float v1 = bilerp7(t1, y0, y1, wy, x0, x1, wx);
        g_bias_agent[((size_t)h * AG + a) * NTOK + n] =
            v1 + ahb[((size_t)h * AG + a) * W_ + y] + awb[((size_t)h * AG + a) * W_ + x];

        const float* t2 = na + ((size_t)h * AG + a) * 49;
        float v2 = bilerp7(t2, y0, y1, wy, x0, x1, wx);
        g_bias_q[((size_t)h * NTOK + n) * AG + a] =
            v2 + hab[((size_t)h * W_ + y) * AG + a] + wab[((size_t)h * W_ + x) * AG + a];
    }
}

// K2: agent token pooling: 8x8 mean over q_img (B,H,W,C) -> (B,49,C)
__global__ __launch_bounds__(256) void k_pool()
{
    int idx = blockIdx.x * 256 + threadIdx.x;   // over B_*AG*C_ = 401408
    int c = idx & 511;
    int a = (idx >> 9) % AG;
    int b = idx / (AG * C_);
    int ay = a / 7, ax = a % 7;
    float s = 0.f;
    #pragma unroll
    for (int dy = 0; dy < 8; dy++)
        for (int dx = 0; dx < 8; dx++)
            s += g_q[((size_t)(b * NTOK + (ay * 8 + dy) * W_ + ax * 8 + dx)) * C_ + c];
    g_at[idx] = s * (1.0f / 64.0f);
}

// K3: agent logits (b,h): logits[a][n] = scale*<ah_a, k_n> + bias_agent[h][a][n]
__global__ __launch_bounds__(256) void k_agent_logits()
{
    int bh = blockIdx.y;
    int b = bh >> 3, h = bh & 7;
    __shared__ __align__(16) float s_ah[AG * HD];
    for (int i = threadIdx.x; i < AG * HD; i += 256) {
        int a = i >> 6, d = i & 63;
        s_ah[i] = g_at[((size_t)b * AG + a) * C_ + h * HD + d] * 0.125f;
    }
    __syncthreads();

    int n = blockIdx.x * 256 + threadIdx.x;
    if (n >= NTOK) return;

    const float4* kp = (const float4*)(g_k + ((size_t)(b * NTOK + n)) * C_ + h * HD);
    float4 kr[16];
    #pragma unroll
    for (int i = 0; i < 16; i++) kr[i] = kp[i];

    const float4* ah4 = (const float4*)s_ah;
    for (int a = 0; a < AG; a++) {
        float acc = g_bias_agent[((size_t)h * AG + a) * NTOK + n];
        #pragma unroll
        for (int i = 0; i < 16; i++) {
            float4 av = ah4[a * 16 + i];
            acc += kr[i].x * av.x + kr[i].y * av.y + kr[i].z * av.z + kr[i].w * av.w;
        }
        g_logits[((size_t)bh * AG + a) * NTOK + n] = acc;
    }
}

// K4: softmax over n=3136 per (b,h,a) row, in-place on g_logits
__global__ __launch_bounds__(256) void k_softmax()
{
    float* row = g_logits + (size_t)blockIdx.x * NTOK;
    __shared__ float red[256];
    int t = threadIdx.x;

    float m = -1e30f;
    for (int i = t; i < NTOK; i += 256) m = fmaxf(m, row[i]);
    red[t] = m; __syncthreads();
    for (int s = 128; s > 0; s >>= 1) { if (t < s) red[t] = fmaxf(red[t], red[t + s]); __syncthreads(); }
    m = red[0]; __syncthreads();

    float sum = 0.f;
    for (int i = t; i < NTOK; i += 256) { float e = __expf(row[i] - m); row[i] = e; sum += e; }
    red[t] = sum; __syncthreads();
    for (int s = 128; s > 0; s >>= 1) { if (t < s) red[t] += red[t + s]; __syncthreads(); }
    float inv = 1.0f / red[0];

    for (int i = t; i < NTOK; i += 256) row[i] *= inv;
}

// K5: agent_v[b,h,a,d] = sum_n attn[a][n] * v[b,n,h*64+d]
__global__ __launch_bounds__(256) void k_agent_v()
{
    int bh = blockIdx.x;
    int b = bh >> 3, h = bh & 7;
    __shared__ float s_at[AG][64];
    __shared__ float s_v[64][64];
    int tid = threadIdx.x;
    int d = tid & 63;
    int as = tid >> 6;   // 0..3

    float acc[13];
    #pragma unroll
    for (int j = 0; j < 13; j++) acc[j] = 0.f;

    for (int n0 = 0; n0 < NTOK; n0 += 64) {
        for (int i = tid; i < 64 * 64; i += 256) {
            int r = i >> 6, c = i & 63;
            s_v[r][c] = g_v[((size_t)(b * NTOK + n0 + r)) * C_ + h * HD + c];
        }
        for (int i = tid; i < AG * 64; i += 256) {
            int a = i >> 6, c = i & 63;
            s_at[a][c] = g_logits[((size_t)bh * AG + a) * NTOK + n0 + c];
        }
        __syncthreads();
        for (int nn = 0; nn < 64; nn++) {
            float vv = s_v[nn][d];
            #pragma unroll
            for (int j = 0; j < 13; j++) {
                int a = as + j * 4;
                if (a < AG) acc[j] += s_at[a][nn] * vv;
            }
        }
        __syncthreads();
    }
    #pragma unroll
    for (int j = 0; j < 13; j++) {
        int a = as + j * 4;
        if (a < AG) g_av[((size_t)bh * AG + a) * HD + d] = acc[j];
    }
}

// K6: q-attention (softmax over 49 agents) + fused depthwise 3x3 conv on v.
// Writes result directly as fp16 into g_xh (the proj GEMM's A operand).
__global__ __launch_bounds__(128) void k_qattn(const float* __restrict__ dwc_w,
                                               const float* __restrict__ dwc_b)
{
    int bh = blockIdx.y;
    int b = bh >> 3, h = bh & 7;
    __shared__ __align__(16) float s_ah[AG * HD];
    __shared__ __align__(16) float s_av[AG * HD];
    __shared__ __align__(16) float s_w[9][64];   // dwc weights for this head's 64 channels
    __shared__ __align__(16) float s_b[64];
    for (int i = threadIdx.x; i < AG * HD; i += 128) {
        int a = i >> 6, d = i & 63;
        s_ah[i] = g_at[((size_t)b * AG + a) * C_ + h * HD + d];
        s_av[i] = g_av[((size_t)bh * AG + a) * HD + d];
    }
    for (int i = threadIdx.x; i < 9 * 64; i += 128) {
        int j = i / 64, ci = i % 64;
        s_w[j][ci] = dwc_w[(size_t)(h * 64 + ci) * 9 + j];
    }
    if (threadIdx.x < 64) s_b[threadIdx.x] = dwc_b[h * 64 + threadIdx.x];
    __syncthreads();

    int n = blockIdx.x * 128 + threadIdx.x;
    if (n >= NTOK) return;

    const float4* qp = (const float4*)(g_q + ((size_t)(b * NTOK + n)) * C_ + h * HD);
    float4 qr[16];
    #pragma unroll
    for (int i = 0; i < 16; i++) {
        float4 t = qp[i];
        t.x *= 0.125f; t.y *= 0.125f; t.z *= 0.125f; t.w *= 0.125f;
        qr[i] = t;
    }

    const float* bq = g_bias_q + ((size_t)h * NTOK + n) * AG;
    float lg[AG];
    float m = -1e30f;
    const float4* ah4 = (const float4*)s_ah;
    for (int a = 0; a < AG; a++) {
        float acc = bq[a];
        #pragma unroll
        for (int i = 0; i < 16; i++) {
            float4 av = ah4[a * 16 + i];
            acc += qr[i].x * av.x + qr[i].y * av.y + qr[i].z * av.z + qr[i].w * av.w;
        }
        lg[a] = acc;
        m = fmaxf(m, acc);
    }
    float s = 0.f;
    for (int a = 0; a < AG; a++) { float e = __expf(lg[a] - m); lg[a] = e; s += e; }
    float inv = 1.0f / s;

    float4 o[16];
    #pragma unroll
    for (int i = 0; i < 16; i++) o[i] = make_float4(0.f, 0.f, 0.f, 0.f);
    const float4* av4 = (const float4*)s_av;
    for (int a = 0; a < AG; a++) {
        float w = lg[a] * inv;
        #pragma unroll
        for (int i = 0; i < 16; i++) {
            float4 v = av4[a * 16 + i];
            o[i].x += w * v.x; o[i].y += w * v.y; o[i].z += w * v.z; o[i].w += w * v.w;
        }
    }

    // fused depthwise 3x3 conv on v for channels [h*64, h*64+64)
    int y = n / W_, x = n % W_;
    const float4* wb4 = (const float4*)s_b;
    #pragma unroll
    for (int i = 0; i < 16; i++) {
        float4 bb = wb4[i];
        o[i].x += bb.x; o[i].y += bb.y; o[i].z += bb.z; o[i].w += bb.w;
    }
    #pragma unroll
    for (int dy = -1; dy <= 1; dy++) {
        int yy = y + dy;
        if (yy < 0 || yy >= H_) continue;
        #pragma unroll
        for (int dx = -1; dx <= 1; dx++) {
            int xx = x + dx;
            if (xx < 0 || xx >= W_) continue;
            int j = (dy + 1) * 3 + (dx + 1);
            const float4* vp = (const float4*)(g_v + ((size_t)(b * NTOK + yy * W_ + xx)) * C_ + h * HD);
            const float4* wj = (const float4*)&s_w[j][0];
            #pragma unroll
            for (int i = 0; i < 16; i++) {
                float4 v = vp[i];
                float4 w = wj[i];
                o[i].x += v.x * w.x; o[i].y += v.y * w.y;
                o[i].z += v.z * w.z; o[i].w += v.w * w.w;
            }
        }
    }

    // write fp16 directly into proj GEMM's A operand
    uint2* op = (uint2*)(g_xh + ((size_t)(b * NTOK + n)) * C_ + h * HD);
    #pragma unroll
    for (int i = 0; i < 16; i++) {
        uint2 u;
        u.x = pack_half2(o[i].x, o[i].y);
        u.y = pack_half2(o[i].z, o[i].w);
        op[i] = u;
    }
}

// ---------------- launch ----------------
extern "C" void kernel_launch(void* const* d_in, const int* in_sizes, int n_in,
                              void* d_out, int out_size)
{
    int base = (n_in >= 15 && in_sizes[1] == 1) ? 3 : 1;

    const float* x      = (const float*)d_in[0];
    const float* q_w    = (const float*)d_in[base + 0];
    const float* kv_w   = (const float*)d_in[base + 1];
    const float* proj_w = (const float*)d_in[base + 2];
    const float* proj_b = (const float*)d_in[base + 3];
    const float* dwc_w  = (const float*)d_in[base + 4];
    const float* dwc_b  = (const float*)d_in[base + 5];
    const float* an_b   = (const float*)d_in[base + 6];
    const float* na_b   = (const float*)d_in[base + 7];
    const float* ah_b   = (const float*)d_in[base + 8];
    const float* aw_b   = (const float*)d_in[base + 9];
    const float* ha_b   = (const float*)d_in[base + 10];
    const float* wa_b   = (const float*)d_in[base + 11];
    float* out = (float*)d_out;

    cudaFuncSetAttribute(hf_gemm<false>, cudaFuncAttributeMaxDynamicSharedMemorySize, GEMM_SMEM);
    cudaFuncSetAttribute(hf_gemm<true>,  cudaFuncAttributeMaxDynamicSharedMemorySize, GEMM_SMEM);

    k_bias<<<98, 256>>>(an_b, na_b, ah_b, aw_b, ha_b, wa_b);
    k_half_w<<<(2048 * C_) / 1024, 256>>>(q_w, kv_w, proj_w);
    k_half_x<<<(int)(((size_t)MTOK * C_) / 1024), 256>>>(x);
    hf_gemm<false><<<dim3(12, MTOK / 128), 256, GEMM_SMEM>>>(nullptr, nullptr);
    k_pool<<<(B_ * AG * C_) / 256, 256>>>();
    k_agent_logits<<<dim3((NTOK + 255) / 256, B_ * HEADS), 256>>>();
    k_softmax<<<B_ * HEADS * AG, 256>>>();
    k_agent_v<<<B_ * HEADS, 256>>>();
    k_qattn<<<dim3((NTOK + 127) / 128, B_ * HEADS), 128>>>(dwc_w, dwc_b);
    hf_gemm<true><<<dim3(4, MTOK / 128), 256, GEMM_SMEM>>>(proj_b, out);
}

// round 9
// speedup vs baseline: 2.7113x; 1.1780x over previous
#include <cuda_runtime.h>
#include <cuda_fp16.h>
#include <cstdint>
#include <math.h>

// ---------------- problem constants ----------------
constexpr int B_    = 16;
constexpr int C_    = 512;
constexpr int H_    = 56;
constexpr int W_    = 56;
constexpr int NTOK  = H_ * W_;        // 3136
constexpr int MTOK  = B_ * NTOK;      // 50176
constexpr int HEADS = 8;
constexpr int HD    = 64;
constexpr int AG    = 49;             // agent tokens
constexpr int NSPL  = 7;              // kv-splits for fused agent attention (7*448 = 3136)

// ---------------- scratch (device globals: allocation-free) ----------------
__device__ float g_q [MTOK * C_];
__device__ float g_k [MTOK * C_];
__device__ float g_v [MTOK * C_];
__device__ float g_at[B_ * AG * C_];               // agent tokens
__device__ float g_av[B_ * HEADS * AG * HD];       // agent_v
__device__ float g_bias_agent[HEADS * AG * NTOK];  // pb1 + pb2  [h][a][n]
__device__ float g_bias_q    [HEADS * NTOK * AG];  // ab1 + ab2  [h][n][a]

// split-KV partials for fused agent attention
__device__ float g_pm [B_ * HEADS * NSPL * AG];
__device__ float g_ps [B_ * HEADS * NSPL * AG];
__device__ float g_pav[B_ * HEADS * NSPL * AG * HD];

// fp16 GEMM operand buffers
__device__ __half g_xh[MTOK * C_];    // A matrix: x (for qkv), then attn+dwc output (for proj)
__device__ __half g_wh[2048 * C_];    // rows: 0-511 q_w, 512-1535 kv_w, 1536-2047 proj_w

// ---------------- helpers ----------------
__device__ __forceinline__ uint32_t h2_as_u32(__half2 h) {
    union { __half2 h; uint32_t u; } cvt;
    cvt.h = h;
    return cvt.u;
}
__device__ __forceinline__ uint32_t pack_half2(float a, float b) {
    return h2_as_u32(__floats2half2_rn(a, b));
}
__device__ __forceinline__ uint32_t smem_u32(const void* p) {
    uint32_t a;
    asm("{ .reg .u64 t; cvta.to.shared.u64 t, %1; cvt.u32.u64 %0, t; }" : "=r"(a) : "l"(p));
    return a;
}
__device__ __forceinline__ float warp_max(float v) {
    #pragma unroll
    for (int o = 16; o > 0; o >>= 1) v = fmaxf(v, __shfl_xor_sync(0xffffffffu, v, o));
    return v;
}
__device__ __forceinline__ float warp_sum(float v) {
    #pragma unroll
    for (int o = 16; o > 0; o >>= 1) v += __shfl_xor_sync(0xffffffffu, v, o);
    return v;
}
#define LDSM_X4(r, addr) \
    asm volatile("ldmatrix.sync.aligned.m8n8.x4.shared.b16 {%0,%1,%2,%3}, [%4];" \
        : "=r"((r)[0]), "=r"((r)[1]), "=r"((r)[2]), "=r"((r)[3]) : "r"(addr))

__device__ __forceinline__ void mma_f16(float c[4], const uint32_t a[4], const uint32_t b[2]) {
    asm volatile("mma.sync.aligned.m16n8k16.row.col.f32.f16.f16.f32 "
        "{%0,%1,%2,%3}, {%4,%5,%6,%7}, {%8,%9}, {%0,%1,%2,%3};"
        : "+f"(c[0]), "+f"(c[1]), "+f"(c[2]), "+f"(c[3])
        : "r"(a[0]), "r"(a[1]), "r"(a[2]), "r"(a[3]), "r"(b[0]), "r"(b[1]));
}
#define CP_ASYNC16(dst, src) \
    asm volatile("cp.async.cg.shared.global [%0], [%1], 16;" :: "r"(dst), "l"(src))
#define CP_COMMIT() asm volatile("cp.async.commit_group;")

// ---------------- convert kernels: fp32 -> fp16 ----------------
__global__ __launch_bounds__(256) void k_half_x(const float* __restrict__ src) {
    size_t i = ((size_t)blockIdx.x * 256 + threadIdx.x) * 4;
    float4 v = *(const float4*)(src + i);
    uint2 u;
    u.x = pack_half2(v.x, v.y);
    u.y = pack_half2(v.z, v.w);
    *(uint2*)(g_xh + i) = u;
}
__global__ __launch_bounds__(256) void k_half_w(const float* __restrict__ qw,
                                                const float* __restrict__ kvw,
                                                const float* __restrict__ pw) {
    size_t i = ((size_t)blockIdx.x * 256 + threadIdx.x) * 4;   // over 2048*512
    size_t row = i >> 9;
    const float* src;
    if (row < 512)        src = qw + i;
    else if (row < 1536)  src = kvw + (i - (size_t)512 * 512);
    else                  src = pw + (i - (size_t)1536 * 512);
    float4 v = *(const float4*)src;
    uint2 u;
    u.x = pack_half2(v.x, v.y);
    u.y = pack_half2(v.z, v.w);
    *(uint2*)(g_wh + i) = u;
}

// ---------------- fp16 GEMM: C(M,N) = A(M,512) * W(N,512)^T ----------------
// CTA 128x128, 8 warps (4x2, warp tile 32x64), K chunks of 32, 4-stage cp.async pipe.
constexpr int T_ROWB = 80;                       // 32 fp16 (64B) + 16B pad per row
constexpr int TILE_B = 128 * T_ROWB;             // 10240 B
constexpr int STAGE_B = 2 * TILE_B;              // A, B
constexpr int NSTAGE = 4;
constexpr int GEMM_SMEM = NSTAGE * STAGE_B;      // 81920 B

template <bool PROJ>
__global__ __launch_bounds__(256) void hf_gemm(const float* __restrict__ pb,
                                               float* __restrict__ out)
{
    extern __shared__ char smem[];
    const uint32_t sb = smem_u32(smem);
    const int tid = threadIdx.x;
    const int lane = tid & 31, wid = tid >> 5;
    const int warp_m = wid & 3, warp_n = wid >> 2;
    const int bm = blockIdx.y, bn = blockIdx.x;
    const int j0 = bn * 128;
    const int wrow0 = (PROJ ? 1536 : 0) + j0;
    const size_t arow0 = (size_t)bm * 128;

    float acc[2][8][4] = {};

    auto load_chunk = [&](int chunk, int stage) {
        const int k0 = chunk * 32;
        const uint32_t dstb = sb + stage * STAGE_B;
        #pragma unroll
        for (int i = 0; i < 4; i++) {
            int u = i * 256 + tid;      // 0..1023
            int t = u >> 9;             // 0 = A, 1 = B
            int s = u & 511;
            int r = s >> 2;             // row 0..127
            int c = s & 3;              // 16B segment
            uint32_t dst = dstb + t * TILE_B + r * T_ROWB + c * 16;
            const __half* src = (t == 0)
                ? g_xh + (arow0 + r) * C_ + k0 + c * 8
                : g_wh + (size_t)(wrow0 + r) * C_ + k0 + c * 8;
            CP_ASYNC16(dst, src);
        }
        CP_COMMIT();
    };

    load_chunk(0, 0);
    load_chunk(1, 1);
    load_chunk(2, 2);

    for (int ch = 0; ch < 16; ch++) {
        if (ch < 14)      asm volatile("cp.async.wait_group 2;");
        else if (ch == 14) asm volatile("cp.async.wait_group 1;");
        else               asm volatile("cp.async.wait_group 0;");
        __syncthreads();
        if (ch + 3 < 16) load_chunk(ch + 3, (ch + 3) & 3);

        const uint32_t stb = sb + (ch & 3) * STAGE_B;
        const uint32_t ahb = stb;
        const uint32_t bhb = stb + TILE_B;

        #pragma unroll
        for (int kk = 0; kk < 32; kk += 16) {
            uint32_t AH[2][4], BH[4][4];
            // A: lanes 0-15 -> rows (k low 8), lanes 16-31 -> (k high 8)
            int ar = warp_m * 32 + (lane & 15);
            int acb = (kk + ((lane >> 4) << 3)) * 2;
            #pragma unroll
            for (int mi = 0; mi < 2; mi++)
                LDSM_X4(AH[mi], ahb + (ar + mi * 16) * T_ROWB + acb);
            // B: x4 covers 2 n-atoms
            int br = warp_n * 64 + (lane & 7) + ((lane >> 4) << 3);
            int bcb = (kk + (((lane >> 3) & 1) << 3)) * 2;
            #pragma unroll
            for (int pi = 0; pi < 4; pi++)
                LDSM_X4(BH[pi], bhb + (br + pi * 16) * T_ROWB + bcb);

            #pragma unroll
            for (int mi = 0; mi < 2; mi++)
                #pragma unroll
                for (int ni = 0; ni < 8; ni++)
                    mma_f16(acc[mi][ni], AH[mi], &BH[ni >> 1][(ni & 1) * 2]);
        }
    }

    // epilogue
    {
        int qr = lane >> 2, qc = lane & 3;
        float* O; int colbase;
        if (PROJ) { O = out; colbase = j0; }
        else {
            if (j0 < 512)        { O = g_q; colbase = j0; }
            else if (j0 < 1024)  { O = g_k; colbase = j0 - 512; }
            else                 { O = g_v; colbase = j0 - 1024; }
        }
        #pragma unroll
        for (int mi = 0; mi < 2; mi++) {
            #pragma unroll
            for (int ni = 0; ni < 8; ni++) {
                int row = bm * 128 + warp_m * 32 + mi * 16 + qr;
                int gcol = colbase + warp_n * 64 + ni * 8 + qc * 2;
                float b0 = 0.f, b1 = 0.f;
                if (PROJ) { b0 = pb[gcol]; b1 = pb[gcol + 1]; }
                *(float2*)&O[(size_t)row * 512 + gcol] =
                    make_float2(acc[mi][ni][0] + b0, acc[mi][ni][1] + b1);
                *(float2*)&O[(size_t)(row + 8) * 512 + gcol] =
                    make_float2(acc[mi][ni][2] + b0, acc[mi][ni][3] + b1);
            }
        }
    }
}

// ---------------- bilinear (jax.image.resize 7 -> 56, clamp-edge) ----------------
__device__ __forceinline__ float bilerp7(const float* t, int y0, int y1, float wy,
                                         int x0, int x1, float wx) {
    float v00 = t[y0 * 7 + x0], v01 = t[y0 * 7 + x1];
    float v10 = t[y1 * 7 + x0], v11 = t[y1 * 7 + x1];
    float a = v00 + (v01 - v00) * wx;
    float b = v10 + (v11 - v10) * wx;
    return a + (b - a) * wy;
}

// K0: precompute both positional-bias tables
__global__ __launch_bounds__(256) void k_bias(
    const float* __restrict__ an, const float* __restrict__ na,
    const float* __restrict__ ahb, const float* __restrict__ awb,
    const float* __restrict__ hab, const float* __restrict__ wab)
{
    int idx = blockIdx.x * 256 + threadIdx.x;          // over HEADS*NTOK = 25088
    if (idx >= HEADS * NTOK) return;
    int h = idx / NTOK;
    int n = idx % NTOK;
    int y = n / W_, x = n % W_;

    float fy = (y + 0.5f) * 0.125f - 0.5f;
    int iy = (int)floorf(fy);
    float wy = fy - (float)iy;
    int y0 = max(iy, 0), y1 = min(iy + 1, 6);

    float fx = (x + 0.5f) * 0.125f - 0.5f;
    int ix = (int)floorf(fx);
    float wx = fx - (float)ix;
    int x0 = max(ix, 0), x1 = min(ix + 1, 6);

    for (int a = 0; a < AG; a++) {
        const float* t1 = an + ((size_t)h * AG + a) * 49;
        float v1 = bilerp7(t1, y0, y1, wy, x0, x1, wx);
        g_bias_agent[((size_t)h * AG + a) * NTOK + n] =
            v1 + ahb[((size_t)h * AG + a) * W_ + y] + awb[((size_t)h * AG + a) * W_ + x];

        const float* t2 = na + ((size_t)h * AG + a) * 49;
        float v2 = bilerp7(t2, y0, y1, wy, x0, x1, wx);
        g_bias_q[((size_t)h * NTOK + n) * AG + a] =
            v2 + hab[((size_t)h * W_ + y) * AG + a] + wab[((size_t)h * W_ + x) * AG + a];
    }
}

// K2: agent token pooling: 8x8 mean over q_img (B,H,W,C) -> (B,49,C)
__global__ __launch_bounds__(256) void k_pool()
{
    int idx = blockIdx.x * 256 + threadIdx.x;   // over B_*AG*C_ = 401408
    int c = idx & 511;
    int a = (idx >> 9) % AG;
    int b = idx / (AG * C_);
    int ay = a / 7, ax = a % 7;
    float s = 0.f;
    #pragma unroll
    for (int dy = 0; dy < 8; dy++)
        for (int dx = 0; dx < 8; dx++)
            s += g_q[((size_t)(b * NTOK + (ay * 8 + dy) * W_ + ax * 8 + dx)) * C_ + c];
    g_at[idx] = s * (1.0f / 64.0f);
}

// K3: fused agent attention (logits + online softmax + agent_v), split-KV.
// grid (NSPL, B*HEADS). Each CTA: 448 tokens in 7 tiles of 64. Warp w owns
// agents a = w + 8j. Lane owns token-pair / dim-pair (2*lane, 2*lane+1).
__global__ __launch_bounds__(256) void k_agent_attn()
{
    __shared__ float s_ah[AG * HD];          // agents (pre-scaled)
    __shared__ float s_kT[64 * 66];          // K tile transposed [d][nl], pad 66
    __shared__ float s_v [64 * 64];          // V tile [nl][d]
    __shared__ float s_p [8][64];            // per-warp softmax weights

    int tid = threadIdx.x, w = tid >> 5, lane = tid & 31;
    int bh = blockIdx.y, b = bh >> 3, h = bh & 7;
    int split = blockIdx.x;
    int n_base = split * 448;

    for (int i = tid; i < AG * HD; i += 256) {
        int a = i >> 6, d = i & 63;
        s_ah[i] = g_at[((size_t)b * AG + a) * C_ + h * HD + d] * 0.125f;
    }

    const int nA = (w == 0) ? 7 : 6;
    float m7[7], s7[7], av0[7], av1[7];
    #pragma unroll
    for (int j = 0; j < 7; j++) { m7[j] = -1e30f; s7[j] = 0.f; av0[j] = 0.f; av1[j] = 0.f; }

    for (int t = 0; t < 7; t++) {
        int n0 = n_base + t * 64;
        __syncthreads();
        #pragma unroll
        for (int i = 0; i < 4; i++) {
            int id = i * 256 + tid;          // 0..1023 float4 slots
            int tok = id >> 4, c4 = id & 15;
            size_t gofs = ((size_t)(b * NTOK + n0 + tok)) * C_ + h * HD + c4 * 4;
            float4 kv = *(const float4*)(g_k + gofs);
            s_kT[(c4 * 4 + 0) * 66 + tok] = kv.x;
            s_kT[(c4 * 4 + 1) * 66 + tok] = kv.y;
            s_kT[(c4 * 4 + 2) * 66 + tok] = kv.z;
            s_kT[(c4 * 4 + 3) * 66 + tok] = kv.w;
            *(float4*)&s_v[tok * 64 + c4 * 4] = *(const float4*)(g_v + gofs);
        }
        __syncthreads();

        for (int j = 0; j < nA; j++) {
            int a = w + 8 * j;
            const float2 bb = *(const float2*)(g_bias_agent +
                ((size_t)h * AG + a) * NTOK + n0 + 2 * lane);
            float l0 = bb.x, l1 = bb.y;
            const float* ahp = s_ah + a * 64;
            #pragma unroll
            for (int d = 0; d < 64; d++) {
                float2 kk = *(const float2*)&s_kT[d * 66 + 2 * lane];
                float aa = ahp[d];
                l0 += aa * kk.x;
                l1 += aa * kk.y;
            }
            float mnew = fmaxf(m7[j], warp_max(fmaxf(l0, l1)));
            float corr = __expf(m7[j] - mnew);
            float p0 = __expf(l0 - mnew), p1 = __expf(l1 - mnew);
            s7[j] = s7[j] * corr + warp_sum(p0 + p1);
            m7[j] = mnew;
            *(float2*)&s_p[w][2 * lane] = make_float2(p0, p1);
            __syncwarp();
            float a0 = av0[j] * corr, a1 = av1[j] * corr;
            #pragma unroll 8
            for (int nl = 0; nl < 64; nl++) {
                float p = s_p[w][nl];
                float2 vv = *(const float2*)&s_v[nl * 64 + 2 * lane];
                a0 += p * vv.x;
                a1 += p * vv.y;
            }
            av0[j] = a0; av1[j] = a1;
            __syncwarp();
        }
    }

    for (int j = 0; j < nA; j++) {
        int a = w + 8 * j;
        size_t base = (size_t)(bh * NSPL + split) * AG + a;
        *(float2*)&g_pav[base * 64 + 2 * lane] = make_float2(av0[j], av1[j]);
        if (lane == 0) { g_pm[base] = m7[j]; g_ps[base] = s7[j]; }
    }
}

// K3b: merge the NSPL split-KV partials -> g_av
__global__ __launch_bounds__(256) void k_agent_combine()
{
    int bh = blockIdx.x;
    for (int i = threadIdx.x; i < AG * HD; i += 256) {
        int a = i >> 6, d = i & 63;
        float M = -1e30f;
        #pragma unroll
        for (int sp = 0; sp < NSPL; sp++)
            M = fmaxf(M, g_pm[(size_t)(bh * NSPL + sp) * AG + a]);
        float S = 0.f, AV = 0.f;
        #pragma unroll
        for (int sp = 0; sp < NSPL; sp++) {
            size_t base = (size_t)(bh * NSPL + sp) * AG + a;
            float e = __expf(g_pm[base] - M);
            S  += g_ps[base] * e;
            AV += g_pav[base * 64 + d] * e;
        }
        g_av[((size_t)bh * AG + a) * HD + d] = AV / S;
    }
}

// K6: q-attention (softmax over 49 agents) + fused depthwise 3x3 conv on v.
// Writes result directly as fp16 into g_xh (the proj GEMM's A operand).
__global__ __launch_bounds__(128) void k_qattn(const float* __restrict__ dwc_w,
                                               const float* __restrict__ dwc_b)
{
    int bh = blockIdx.y;
    int b = bh >> 3, h = bh & 7;
    __shared__ __align__(16) float s_ah[AG * HD];
    __shared__ __align__(16) float s_av[AG * HD];
    __shared__ __align__(16) float s_w[9][64];   // dwc weights for this head's 64 channels
    __shared__ __align__(16) float s_b[64];
    for (int i = threadIdx.x; i < AG * HD; i += 128) {
        int a = i >> 6, d = i & 63;
        s_ah[i] = g_at[((size_t)b * AG + a) * C_ + h * HD + d];
        s_av[i] = g_av[((size_t)bh * AG + a) * HD + d];
    }
    for (int i = threadIdx.x; i < 9 * 64; i += 128) {
        int j = i / 64, ci = i % 64;
        s_w[j][ci] = dwc_w[(size_t)(h * 64 + ci) * 9 + j];
    }
    if (threadIdx.x < 64) s_b[threadIdx.x] = dwc_b[h * 64 + threadIdx.x];
    __syncthreads();

    int n = blockIdx.x * 128 + threadIdx.x;
    if (n >= NTOK) return;

    const float4* qp = (const float4*)(g_q + ((size_t)(b * NTOK + n)) * C_ + h * HD);
    float4 qr[16];
    #pragma unroll
    for (int i = 0; i < 16; i++) {
        float4 t = qp[i];
        t.x *= 0.125f; t.y *= 0.125f; t.z *= 0.125f; t.w *= 0.125f;
        qr[i] = t;
    }

    const float* bq = g_bias_q + ((size_t)h * NTOK + n) * AG;
    float lg[AG];
    float m = -1e30f;
    const float4* ah4 = (const float4*)s_ah;
    for (int a = 0; a < AG; a++) {
        float acc = bq[a];
        #pragma unroll
        for (int i = 0; i < 16; i++) {
            float4 av = ah4[a * 16 + i];
            acc += qr[i].x * av.x + qr[i].y * av.y + qr[i].z * av.z + qr[i].w * av.w;
        }
        lg[a] = acc;
        m = fmaxf(m, acc);
    }
    float s = 0.f;
    for (int a = 0; a < AG; a++) { float e = __expf(lg[a] - m); lg[a] = e; s += e; }
    float inv = 1.0f / s;

    float4 o[16];
    #pragma unroll
    for (int i = 0; i < 16; i++) o[i] = make_float4(0.f, 0.f, 0.f, 0.f);
    const float4* av4 = (const float4*)s_av;
    for (int a = 0; a < AG; a++) {
        float w = lg[a] * inv;
        #pragma unroll
        for (int i = 0; i < 16; i++) {
            float4 v = av4[a * 16 + i];
            o[i].x += w * v.x; o[i].y += w * v.y; o[i].z += w * v.z; o[i].w += w * v.w;
        }
    }

    // fused depthwise 3x3 conv on v for channels [h*64, h*64+64)
    int y = n / W_, x = n % W_;
    const float4* wb4 = (const float4*)s_b;
    #pragma unroll
    for (int i = 0; i < 16; i++) {
        float4 bb = wb4[i];
        o[i].x += bb.x; o[i].y += bb.y; o[i].z += bb.z; o[i].w += bb.w;
    }
    #pragma unroll
    for (int dy = -1; dy <= 1; dy++) {
        int yy = y + dy;
        if (yy < 0 || yy >= H_) continue;
        #pragma unroll
        for (int dx = -1; dx <= 1; dx++) {
            int xx = x + dx;
            if (xx < 0 || xx >= W_) continue;
            int j = (dy + 1) * 3 + (dx + 1);
            const float4* vp = (const float4*)(g_v + ((size_t)(b * NTOK + yy * W_ + xx)) * C_ + h * HD);
            const float4* wj = (const float4*)&s_w[j][0];
            #pragma unroll
            for (int i = 0; i < 16; i++) {
                float4 v = vp[i];
                float4 w = wj[i];
                o[i].x += v.x * w.x; o[i].y += v.y * w.y;
                o[i].z += v.z * w.z; o[i].w += v.w * w.w;
            }
        }
    }

    // write fp16 directly into proj GEMM's A operand
    uint2* op = (uint2*)(g_xh + ((size_t)(b * NTOK + n)) * C_ + h * HD);
    #pragma unroll
    for (int i = 0; i < 16; i++) {
        uint2 u;
        u.x = pack_half2(o[i].x, o[i].y);
        u.y = pack_half2(o[i].z, o[i].w);
        op[i] = u;
    }
}

// ---------------- launch ----------------
extern "C" void kernel_launch(void* const* d_in, const int* in_sizes, int n_in,
                              void* d_out, int out_size)
{
    int base = (n_in >= 15 && in_sizes[1] == 1) ? 3 : 1;

    const float* x      = (const float*)d_in[0];
    const float* q_w    = (const float*)d_in[base + 0];
    const float* kv_w   = (const float*)d_in[base + 1];
    const float* proj_w = (const float*)d_in[base + 2];
    const float* proj_b = (const float*)d_in[base + 3];
    const float* dwc_w  = (const float*)d_in[base + 4];
    const float* dwc_b  = (const float*)d_in[base + 5];
    const float* an_b   = (const float*)d_in[base + 6];
    const float* na_b   = (const float*)d_in[base + 7];
    const float* ah_b   = (const float*)d_in[base + 8];
    const float* aw_b   = (const float*)d_in[base + 9];
    const float* ha_b   = (const float*)d_in[base + 10];
    const float* wa_b   = (const float*)d_in[base + 11];
    float* out = (float*)d_out;

    cudaFuncSetAttribute(hf_gemm<false>, cudaFuncAttributeMaxDynamicSharedMemorySize, GEMM_SMEM);
    cudaFuncSetAttribute(hf_gemm<true>,  cudaFuncAttributeMaxDynamicSharedMemorySize, GEMM_SMEM);

    k_bias<<<98, 256>>>(an_b, na_b, ah_b, aw_b, ha_b, wa_b);
    k_half_w<<<(2048 * C_) / 1024, 256>>>(q_w, kv_w, proj_w);
    k_half_x<<<(int)(((size_t)MTOK * C_) / 1024), 256>>>(x);
    hf_gemm<false><<<dim3(12, MTOK / 128), 256, GEMM_SMEM>>>(nullptr, nullptr);
    k_pool<<<(B_ * AG * C_) / 256, 256>>>();
    k_agent_attn<<<dim3(NSPL, B_ * HEADS), 256>>>();
    k_agent_combine<<<B_ * HEADS, 256>>>();
    k_qattn<<<dim3((NTOK + 127) / 128, B_ * HEADS), 128>>>(dwc_w, dwc_b);
    hf_gemm<true><<<dim3(4, MTOK / 128), 256, GEMM_SMEM>>>(proj_b, out);
}

// round 11
// speedup vs baseline: 3.4508x; 1.2728x over previous
#include <cuda_runtime.h>
#include <cuda_fp16.h>
#include <cstdint>
#include <math.h>

// ---------------- problem constants ----------------
constexpr int B_    = 16;
constexpr int C_    = 512;
constexpr int H_    = 56;
constexpr int W_    = 56;
constexpr int NTOK  = H_ * W_;        // 3136
constexpr int MTOK  = B_ * NTOK;      // 50176
constexpr int HEADS = 8;
constexpr int HD    = 64;
constexpr int AG    = 49;             // agent tokens
constexpr int NSPL  = 7;              // kv-splits for fused agent attention

// ---------------- scratch (device globals: allocation-free) ----------------
__device__ float g_q [MTOK * C_];
__device__ float g_k [MTOK * C_];
__device__ float g_v [MTOK * C_];
__device__ float g_at[B_ * AG * C_];               // agent tokens
__device__ float g_av[B_ * HEADS * AG * HD];       // agent_v
__device__ float g_bias_agent[HEADS * AG * NTOK];  // pb1 + pb2  [h][a][n]
__device__ float g_bias_q    [HEADS * NTOK * AG];  // ab1 + ab2  [h][n][a]

// split-KV partials for fused agent attention
__device__ float g_pm [B_ * HEADS * NSPL * AG];
__device__ float g_ps [B_ * HEADS * NSPL * AG];
__device__ float g_pav[B_ * HEADS * NSPL * AG * HD];

// fp16 GEMM operand buffers
__device__ __half g_xh[MTOK * C_];    // A matrix: x (for qkv), then attn+dwc output (for proj)
__device__ __half g_wh[2048 * C_];    // rows: 0-511 q_w, 512-1535 kv_w, 1536-2047 proj_w
__device__ __half g_qh[MTOK * C_];    // fp16 of q*0.125 for q-attention MMA

// ---------------- helpers ----------------
__device__ __forceinline__ uint32_t h2_as_u32(__half2 h) {
    union { __half2 h; uint32_t u; } cvt;
    cvt.h = h;
    return cvt.u;
}
__device__ __forceinline__ uint32_t pack_half2(float a, float b) {
    return h2_as_u32(__floats2half2_rn(a, b));
}
__device__ __forceinline__ uint32_t smem_u32(const void* p) {
    uint32_t a;
    asm("{ .reg .u64 t; cvta.to.shared.u64 t, %1; cvt.u32.u64 %0, t; }" : "=r"(a) : "l"(p));
    return a;
}
__device__ __forceinline__ float warp_max(float v) {
    #pragma unroll
    for (int o = 16; o > 0; o >>= 1) v = fmaxf(v, __shfl_xor_sync(0xffffffffu, v, o));
    return v;
}
__device__ __forceinline__ float warp_sum(float v) {
    #pragma unroll
    for (int o = 16; o > 0; o >>= 1) v += __shfl_xor_sync(0xffffffffu, v, o);
    return v;
}
#define LDSM_X4(r, addr) \
    asm volatile("ldmatrix.sync.aligned.m8n8.x4.shared.b16 {%0,%1,%2,%3}, [%4];" \
        : "=r"((r)[0]), "=r"((r)[1]), "=r"((r)[2]), "=r"((r)[3]) : "r"(addr))

__device__ __forceinline__ void mma_f16(float c[4], const uint32_t a[4], const uint32_t b[2]) {
    asm volatile("mma.sync.aligned.m16n8k16.row.col.f32.f16.f16.f32 "
        "{%0,%1,%2,%3}, {%4,%5,%6,%7}, {%8,%9}, {%0,%1,%2,%3};"
        : "+f"(c[0]), "+f"(c[1]), "+f"(c[2]), "+f"(c[3])
        : "r"(a[0]), "r"(a[1]), "r"(a[2]), "r"(a[3]), "r"(b[0]), "r"(b[1]));
}
#define CP_ASYNC16(dst, src) \
    asm volatile("cp.async.cg.shared.global [%0], [%1], 16;" :: "r"(dst), "l"(src))
#define CP_COMMIT() asm volatile("cp.async.commit_group;")

// ---------------- convert kernels: fp32 -> fp16 ----------------
__global__ __launch_bounds__(256) void k_half_x(const float* __restrict__ src) {
    size_t i = ((size_t)blockIdx.x * 256 + threadIdx.x) * 4;
    float4 v = *(const float4*)(src + i);
    uint2 u;
    u.x = pack_half2(v.x, v.y);
    u.y = pack_half2(v.z, v.w);
    *(uint2*)(g_xh + i) = u;
}
__global__ __launch_bounds__(256) void k_half_w(const float* __restrict__ qw,
                                                const float* __restrict__ kvw,
                                                const float* __restrict__ pw) {
    size_t i = ((size_t)blockIdx.x * 256 + threadIdx.x) * 4;   // over 2048*512
    size_t row = i >> 9;
    const float* src;
    if (row < 512)        src = qw + i;
    else if (row < 1536)  src = kvw + (i - (size_t)512 * 512);
    else                  src = pw + (i - (size_t)1536 * 512);
    float4 v = *(const float4*)src;
    uint2 u;
    u.x = pack_half2(v.x, v.y);
    u.y = pack_half2(v.z, v.w);
    *(uint2*)(g_wh + i) = u;
}

// ---------------- fp16 GEMM: C(M,N) = A(M,512) * W(N,512)^T ----------------
// CTA 128x128, 8 warps (4x2, warp tile 32x64), K chunks of 64, 3-stage cp.async pipe,
// fragment double-buffering inside each chunk.
constexpr int T_ROWB = 144;                      // 64 fp16 (128B) + 16B pad per row
constexpr int TILE_B = 128 * T_ROWB;             // 18432 B
constexpr int STAGE_B = 2 * TILE_B;              // A, B
constexpr int NSTAGE = 3;
constexpr int GEMM_SMEM = NSTAGE * STAGE_B;      // 110592 B

template <bool PROJ>
__global__ __launch_bounds__(256, 2) void hf_gemm(const float* __restrict__ pb,
                                                  float* __restrict__ out)
{
    extern __shared__ char smem[];
    const uint32_t sb = smem_u32(smem);
    const int tid = threadIdx.x;
    const int lane = tid & 31, wid = tid >> 5;
    const int warp_m = wid & 3, warp_n = wid >> 2;
    const int bm = blockIdx.y, bn = blockIdx.x;
    const int j0 = bn * 128;
    const int wrow0 = (PROJ ? 1536 : 0) + j0;
    const size_t arow0 = (size_t)bm * 128;

    float acc[2][8][4] = {};

    auto load_chunk = [&](int chunk, int stage) {
        const int k0 = chunk * 64;
        const uint32_t dstb = sb + stage * STAGE_B;
        #pragma unroll
        for (int i = 0; i < 8; i++) {
            int u = i * 256 + tid;      // 0..2047
            int t = u >> 10;            // 0 = A, 1 = B
            int s = u & 1023;
            int r = s >> 3;             // row 0..127
            int c = s & 7;              // 16B segment
            uint32_t dst = dstb + t * TILE_B + r * T_ROWB + c * 16;
            const __half* src = (t == 0)
                ? g_xh + (arow0 + r) * C_ + k0 + c * 8
                : g_wh + (size_t)(wrow0 + r) * C_ + k0 + c * 8;
            CP_ASYNC16(dst, src);
        }
        CP_COMMIT();
    };

    load_chunk(0, 0);
    load_chunk(1, 1);

    uint32_t AH[2][2][4], BH[2][4][4];
    const int ar = warp_m * 32 + (lane & 15);
    const int br = warp_n * 64 + (lane & 7) + ((lane >> 4) << 3);

    for (int ch = 0; ch < 8; ch++) {
        if (ch < 7) asm volatile("cp.async.wait_group 1;");
        else        asm volatile("cp.async.wait_group 0;");
        __syncthreads();
        if (ch + 2 < 8) load_chunk(ch + 2, (ch + 2) % NSTAGE);

        const uint32_t stb = sb + (ch % NSTAGE) * STAGE_B;
        const uint32_t ahb = stb;
        const uint32_t bhb = stb + TILE_B;

        auto ldfr = [&](int buf, int kk) {
            int acb = (kk + ((lane >> 4) << 3)) * 2;
            int bcb = (kk + (((lane >> 3) & 1) << 3)) * 2;
            #pragma unroll
            for (int mi = 0; mi < 2; mi++)
                LDSM_X4(AH[buf][mi], ahb + (ar + mi * 16) * T_ROWB + acb);
            #pragma unroll
            for (int pi = 0; pi < 4; pi++)
                LDSM_X4(BH[buf][pi], bhb + (br + pi * 16) * T_ROWB + bcb);
        };

        ldfr(0, 0);
        #pragma unroll
        for (int kk = 0; kk < 4; kk++) {
            if (kk < 3) ldfr((kk + 1) & 1, (kk + 1) * 16);
            int cb = kk & 1;
            #pragma unroll
            for (int mi = 0; mi < 2; mi++)
                #pragma unroll
                for (int ni = 0; ni < 8; ni++)
                    mma_f16(acc[mi][ni], AH[cb][mi], &BH[cb][ni >> 1][(ni & 1) * 2]);
        }
    }

    // epilogue
    {
        int qr = lane >> 2, qc = lane & 3;
        float* O; int colbase;
        if (PROJ) { O = out; colbase = j0; }
        else {
            if (j0 < 512)        { O = g_q; colbase = j0; }
            else if (j0 < 1024)  { O = g_k; colbase = j0 - 512; }
            else                 { O = g_v; colbase = j0 - 1024; }
        }
        #pragma unroll
        for (int mi = 0; mi < 2; mi++) {
            #pragma unroll
            for (int ni = 0; ni < 8; ni++) {
                int row = bm * 128 + warp_m * 32 + mi * 16 + qr;
                int gcol = colbase + warp_n * 64 + ni * 8 + qc * 2;
                float b0 = 0.f, b1 = 0.f;
                if (PROJ) { b0 = pb[gcol]; b1 = pb[gcol + 1]; }
                *(float2*)&O[(size_t)row * 512 + gcol] =
                    make_float2(acc[mi][ni][0] + b0, acc[mi][ni][1] + b1);
                *(float2*)&O[(size_t)(row + 8) * 512 + gcol] =
                    make_float2(acc[mi][ni][2] + b0, acc[mi][ni][3] + b1);
                if (!PROJ && j0 < 512) {
                    // also store fp16 of q*scale for the MMA q-attention
                    *(uint32_t*)(g_qh + (size_t)row * 512 + gcol) =
                        pack_half2(acc[mi][ni][0] * 0.125f, acc[mi][ni][1] * 0.125f);
                    *(uint32_t*)(g_qh + (size_t)(row + 8) * 512 + gcol) =
                        pack_half2(acc[mi][ni][2] * 0.125f, acc[mi][ni][3] * 0.125f);
                }
            }
        }
    }
}

// ---------------- bilinear (jax.image.resize 7 -> 56, clamp-edge) ----------------
__device__ __forceinline__ float bilerp7(const float* t, int y0, int y1, float wy,
                                         int x0, int x1, float wx) {
    float v00 = t[y0 * 7 + x0], v01 = t[y0 * 7 + x1];
    float v10 = t[y1 * 7 + x0], v11 = t[y1 * 7 + x1];
    float a = v00 + (v01 - v00) * wx;
    float b = v10 + (v11 - v10) * wx;
    return a + (b - a) * wy;
}

// K0: precompute both positional-bias tables
__global__ __launch_bounds__(256) void k_bias(
    const float* __restrict__ an, const float* __restrict__ na,
    const float* __restrict__ ahb, const float* __restrict__ awb,
    const float* __restrict__ hab, const float* __restrict__ wab)
{
    int idx = blockIdx.x * 256 + threadIdx.x;          // over HEADS*NTOK = 25088
    if (idx >= HEADS * NTOK) return;
    int h = idx / NTOK;
    int n = idx % NTOK;
    int y = n / W_, x = n % W_;

    float fy = (y + 0.5f) * 0.125f - 0.5f;
    int iy = (int)floorf(fy);
    float wy = fy - (float)iy;
    int y0 = max(iy, 0), y1 = min(iy + 1, 6);

    float fx = (x + 0.5f) * 0.125f - 0.5f;
    int ix = (int)floorf(fx);
    float wx = fx - (float)ix;
    int x0 = max(ix, 0), x1 = min(ix + 1, 6);

    for (int a = 0; a < AG; a++) {
        const float* t1 = an + ((size_t)h * AG + a) * 49;
        float v1 = bilerp7(t1, y0, y1, wy, x0, x1, wx);
        g_bias_agent[((size_t)h * AG + a) * NTOK + n] =
            v1 + ahb[((size_t)h * AG + a) * W_ + y] + awb[((size_t)h * AG + a) * W_ + x];

        const float* t2 = na + ((size_t)h * AG + a) * 49;
        float v2 = bilerp7(t2, y0, y1, wy, x0, x1, wx);
        g_bias_q[((size_t)h * NTOK + n) * AG + a] =
            v2 + hab[((size_t)h * W_ + y) * AG + a] + wab[((size_t)h * W_ + x) * AG + a];
    }
}

// K2: agent token pooling: 8x8 mean over q_img (B,H,W,C) -> (B,49,C)
__global__ __launch_bounds__(256) void k_pool()
{
    int idx = blockIdx.x * 256 + threadIdx.x;   // over B_*AG*C_ = 401408
    int c = idx & 511;
    int a = (idx >> 9) % AG;
    int b = idx / (AG * C_);
    int ay = a / 7, ax = a % 7;
    float s = 0.f;
    #pragma unroll
    for (int dy = 0; dy < 8; dy++)
        for (int dx = 0; dx < 8; dx++)
            s += g_q[((size_t)(b * NTOK + (ay * 8 + dy) * W_ + ax * 8 + dx)) * C_ + c];
    g_at[idx] = s * (1.0f / 64.0f);
}

// K3: fused agent attention (logits + online softmax + agent_v), split-KV, fp32.
__global__ __launch_bounds__(256) void k_agent_attn()
{
    __shared__ float s_ah[AG * HD];          // agents (pre-scaled)
    __shared__ float s_kT[64 * 66];          // K tile transposed [d][nl], pad 66
    __shared__ float s_v [64 * 64];          // V tile [nl][d]
    __shared__ float s_p [8][64];            // per-warp softmax weights

    int tid = threadIdx.x, w = tid >> 5, lane = tid & 31;
    int bh = blockIdx.y, b = bh >> 3, h = bh & 7;
    int split = blockIdx.x;
    int n_base = split * 448;

    for (int i = tid; i < AG * HD; i += 256) {
        int a = i >> 6, d = i & 63;
        s_ah[i] = g_at[((size_t)b * AG + a) * C_ + h * HD + d] * 0.125f;
    }

    const int nA = (w == 0) ? 7 : 6;
    float m7[7], s7[7], av0[7], av1[7];
    #pragma unroll
    for (int j = 0; j < 7; j++) { m7[j] = -1e30f; s7[j] = 0.f; av0[j] = 0.f; av1[j] = 0.f; }

    for (int t = 0; t < 7; t++) {
        int n0 = n_base + t * 64;
        __syncthreads();
        #pragma unroll
        for (int i = 0; i < 4; i++) {
            int id = i * 256 + tid;          // 0..1023 float4 slots
            int tok = id >> 4, c4 = id & 15;
            size_t gofs = ((size_t)(b * NTOK + n0 + tok)) * C_ + h * HD + c4 * 4;
            float4 kv = *(const float4*)(g_k + gofs);
            s_kT[(c4 * 4 + 0) * 66 + tok] = kv.x;
            s_kT[(c4 * 4 + 1) * 66 + tok] = kv.y;
            s_kT[(c4 * 4 + 2) * 66 + tok] = kv.z;
            s_kT[(c4 * 4 + 3) * 66 + tok] = kv.w;
            *(float4*)&s_v[tok * 64 + c4 * 4] = *(const float4*)(g_v + gofs);
        }
        __syncthreads();

        for (int j = 0; j < nA; j++) {
            int a = w + 8 * j;
            const float2 bb = *(const float2*)(g_bias_agent +
                ((size_t)h * AG + a) * NTOK + n0 + 2 * lane);
            float l0 = bb.x, l1 = bb.y;
            const float* ahp = s_ah + a * 64;
            #pragma unroll
            for (int d = 0; d < 64; d++) {
                float2 kk = *(const float2*)&s_kT[d * 66 + 2 * lane];
                float aa = ahp[d];
                l0 += aa * kk.x;
                l1 += aa * kk.y;
            }
            float mnew = fmaxf(m7[j], warp_max(fmaxf(l0, l1)));
            float corr = __expf(m7[j] - mnew);
            float p0 = __expf(l0 - mnew), p1 = __expf(l1 - mnew);
            s7[j] = s7[j] * corr + warp_sum(p0 + p1);
            m7[j] = mnew;
            *(float2*)&s_p[w][2 * lane] = make_float2(p0, p1);
            __syncwarp();
            float a0 = av0[j] * corr, a1 = av1[j] * corr;
            #pragma unroll 8
            for (int nl = 0; nl < 64; nl++) {
                float p = s_p[w][nl];
                float2 vv = *(const float2*)&s_v[nl * 64 + 2 * lane];
                a0 += p * vv.x;
                a1 += p * vv.y;
            }
            av0[j] = a0; av1[j] = a1;
            __syncwarp();
        }
    }

    for (int j = 0; j < nA; j++) {
        int a = w + 8 * j;
        size_t base = (size_t)(bh * NSPL + split) * AG + a;
        *(float2*)&g_pav[base * 64 + 2 * lane] = make_float2(av0[j], av1[j]);
        if (lane == 0) { g_pm[base] = m7[j]; g_ps[base] = s7[j]; }
    }
}

// K3b: merge the NSPL split-KV partials -> g_av (fp32)
__global__ __launch_bounds__(256) void k_agent_combine()
{
    int bh = blockIdx.x;
    for (int i = threadIdx.x; i < AG * HD; i += 256) {
        int a = i >> 6, d = i & 63;
        float M = -1e30f;
        #pragma unroll
        for (int sp = 0; sp < NSPL; sp++)
            M = fmaxf(M, g_pm[(size_t)(bh * NSPL + sp) * AG + a]);
        float S = 0.f, AV = 0.f;
        #pragma unroll
        for (int sp = 0; sp < NSPL; sp++) {
            size_t base = (size_t)(bh * NSPL + sp) * AG + a;
            float e = __expf(g_pm[base] - M);
            S  += g_ps[base] * e;
            AV += g_pav[base * 64 + d] * e;
        }
        g_av[((size_t)bh * AG + a) * HD + d] = AV / S;
    }
}

// K6: q-attention via tensor-core MMA (warp = 32 tokens) + fused dwc, fp16 out -> g_xh.
// logits: q(fp16,*0.125) @ ah^T (agents padded to 64), bias fp32, quad-shuffle softmax,
// P fragments reuse accumulator layout as A operand for P @ agent_v.
__global__ __launch_bounds__(256, 2) void k_qattn_mma(const float* __restrict__ dwc_w,
                                                      const float* __restrict__ dwc_b)
{
    __shared__ __half s_ah [64 * 72];   // [agent][d], row stride 144B
    __shared__ __half s_avT[64 * 72];   // [d][agent], row stride 144B
    __shared__ float  s_w[9][64];
    __shared__ float  s_b[64];

    int tid = threadIdx.x, w = tid >> 5, lane = tid & 31;
    int bh = blockIdx.y, b = bh >> 3, h = bh & 7;

    for (int i = tid; i < 64 * 64; i += 256) {
        int rr = i >> 6, cc = i & 63;
        s_ah [rr * 72 + cc] = (rr < AG)
            ? __float2half(g_at[((size_t)b * AG + rr) * C_ + h * HD + cc]) : __float2half(0.f);
        s_avT[rr * 72 + cc] = (cc < AG)
            ? __float2half(g_av[((size_t)bh * AG + cc) * HD + rr]) : __float2half(0.f);
    }
    for (int i = tid; i < 9 * 64; i += 256)
        s_w[i / 64][i % 64] = dwc_w[(size_t)(h * 64 + (i % 64)) * 9 + i / 64];
    if (tid < 64) s_b[tid] = dwc_b[h * 64 + tid];
    __syncthreads();

    int n0w = blockIdx.x * 256 + w * 32;
    if (n0w >= NTOK) return;           // warp-granular tail (98 warps of 32 tokens)

    const uint32_t sah = smem_u32(s_ah), sav = smem_u32(s_avT);
    const int r = lane >> 2, c2 = (lane & 3) * 2;
    const int lrow = (lane & 7) + ((lane >> 4) << 3);
    const int lcol = (((lane >> 3) & 1) << 3);

    // ---- logits MMA: acc[mi][na] covers tokens (n0w+16mi+r, +8), agents (8na+c2, +1)
    float acc[2][8][4] = {};
    const __half* qb = g_qh + ((size_t)(b * NTOK + n0w)) * C_ + h * HD;
    #pragma unroll
    for (int ks = 0; ks < 4; ks++) {
        uint32_t BH[4][4];
        #pragma unroll
        for (int pi = 0; pi < 4; pi++)
            LDSM_X4(BH[pi], sah + (pi * 16 + lrow) * 144 + (ks * 16 + lcol) * 2);
        #pragma unroll
        for (int mi = 0; mi < 2; mi++) {
            const __half* qq = qb + (size_t)(mi * 16 + r) * C_ + ks * 16 + c2;
            uint32_t A[4];
            A[0] = *(const uint32_t*)(qq);
            A[1] = *(const uint32_t*)(qq + 8 * C_);
            A[2] = *(const uint32_t*)(qq + 8);
            A[3] = *(const uint32_t*)(qq + 8 * C_ + 8);
            #pragma unroll
            for (int na = 0; na < 8; na++)
                mma_f16(acc[mi][na], A, &BH[na >> 1][(na & 1) * 2]);
        }
    }

    // ---- bias + mask + softmax (per row; row spread over 4 lanes of the quad)
    uint32_t pa[2][8][2];
    #pragma unroll
    for (int mi = 0; mi < 2; mi++) {
        int t0 = n0w + mi * 16 + r;
        float m0 = -1e30f, m1 = -1e30f;
        #pragma unroll
        for (int na = 0; na < 8; na++) {
            int a0 = na * 8 + c2;
            if (a0 < AG) {
                const float* bp0 = g_bias_q + ((size_t)h * NTOK + t0) * AG + a0;
                const float* bp1 = g_bias_q + ((size_t)h * NTOK + t0 + 8) * AG + a0;
                acc[mi][na][0] += bp0[0];
                acc[mi][na][2] += bp1[0];
                if (a0 + 1 < AG) { acc[mi][na][1] += bp0[1]; acc[mi][na][3] += bp1[1]; }
                else             { acc[mi][na][1] = -1e30f;  acc[mi][na][3] = -1e30f; }
            } else {
                acc[mi][na][0] = acc[mi][na][1] = -1e30f;
                acc[mi][na][2] = acc[mi][na][3] = -1e30f;
            }
            m0 = fmaxf(m0, fmaxf(acc[mi][na][0], acc[mi][na][1]));
            m1 = fmaxf(m1, fmaxf(acc[mi][na][2], acc[mi][na][3]));
        }
        m0 = fmaxf(m0, __shfl_xor_sync(0xffffffffu, m0, 1));
        m0 = fmaxf(m0, __shfl_xor_sync(0xffffffffu, m0, 2));
        m1 = fmaxf(m1, __shfl_xor_sync(0xffffffffu, m1, 1));
        m1 = fmaxf(m1, __shfl_xor_sync(0xffffffffu, m1, 2));
        float s0 = 0.f, s1 = 0.f;
        #pragma unroll
        for (int na = 0; na < 8; na++) {
            acc[mi][na][0] = __expf(acc[mi][na][0] - m0);
            acc[mi][na][1] = __expf(acc[mi][na][1] - m0);
            acc[mi][na][2] = __expf(acc[mi][na][2] - m1);
            acc[mi][na][3] = __expf(acc[mi][na][3] - m1);
            s0 += acc[mi][na][0] + acc[mi][na][1];
            s1 += acc[mi][na][2] + acc[mi][na][3];
        }
        s0 += __shfl_xor_sync(0xffffffffu, s0, 1);
        s0 += __shfl_xor_sync(0xffffffffu, s0, 2);
        s1 += __shfl_xor_sync(0xffffffffu, s1, 1);
        s1 += __shfl_xor_sync(0xffffffffu, s1, 2);
        float i0 = 1.0f / s0, i1 = 1.0f / s1;
        #pragma unroll
        for (int na = 0; na < 8; na++) {
            pa[mi][na][0] = pack_half2(acc[mi][na][0] * i0, acc[mi][na][1] * i0);
            pa[mi][na][1] = pack_half2(acc[mi][na][2] * i1, acc[mi][na][3] * i1);
        }
    }

    // ---- P @ agent_v : o[mi][na] covers tokens as above, d = 8na+c2(+1)
    float o[2][8][4] = {};
    #pragma unroll
    for (int ks = 0; ks < 4; ks++) {
        uint32_t BH[4][4];
        #pragma unroll
        for (int pi = 0; pi < 4; pi++)
            LDSM_X4(BH[pi], sav + (pi * 16 + lrow) * 144 + (ks * 16 + lcol) * 2);
        #pragma unroll
        for (int mi = 0; mi < 2; mi++) {
            uint32_t A[4] = { pa[mi][2 * ks][0], pa[mi][2 * ks][1],
                              pa[mi][2 * ks + 1][0], pa[mi][2 * ks + 1][1] };
            #pragma unroll
            for (int na = 0; na < 8; na++)
                mma_f16(o[mi][na], A, &BH[na >> 1][(na & 1) * 2]);
        }
    }

    // ---- fused dwc (fp32) + fp16 store to g_xh
    #pragma unroll
    for (int mi = 0; mi < 2; mi++) {
        #pragma unroll
        for (int rh = 0; rh < 2; rh++) {
            int t = n0w + mi * 16 + r + rh * 8;
            int y = t / W_, x = t % W_;
            float v0[8], v1[8];
            #pragma unroll
            for (int na = 0; na < 8; na++) {
                v0[na] = o[mi][na][rh * 2 + 0] + s_b[na * 8 + c2];
                v1[na] = o[mi][na][rh * 2 + 1] + s_b[na * 8 + c2 + 1];
            }
            #pragma unroll
            for (int dy = -1; dy <= 1; dy++) {
                int yy = y + dy;
                if (yy < 0 || yy >= H_) continue;
                #pragma unroll
                for (int dx = -1; dx <= 1; dx++) {
                    int xx = x + dx;
                    if (xx < 0 || xx >= W_) continue;
                    int j = (dy + 1) * 3 + (dx + 1);
                    const float* vb = g_v + ((size_t)(b * NTOK + yy * W_ + xx)) * C_ + h * HD;
                    #pragma unroll
                    for (int na = 0; na < 8; na++) {
                        float2 vv = *(const float2*)(vb + na * 8 + c2);
                        float2 ww = *(const float2*)(&s_w[j][na * 8 + c2]);
                        v0[na] += vv.x * ww.x;
                        v1[na] += vv.y * ww.y;
                    }
                }
            }
            __half* ob = g_xh + ((size_t)(b * NTOK + t)) * C_ + h * HD;
            #pragma unroll
            for (int na = 0; na < 8; na++)
                *(uint32_t*)(ob + na * 8 + c2) = pack_half2(v0[na], v1[na]);
        }
    }
}

// ---------------- launch ----------------
extern "C" void kernel_launch(void* const* d_in, const int* in_sizes, int n_in,
                              void* d_out, int out_size)
{
    int base = (n_in >= 15 && in_sizes[1] == 1) ? 3 : 1;

    const float* x      = (const float*)d_in[0];
    const float* q_w    = (const float*)d_in[base + 0];
    const float* kv_w   = (const float*)d_in[base + 1];
    const float* proj_w = (const float*)d_in[base + 2];
    const float* proj_b = (const float*)d_in[base + 3];
    const float* dwc_w  = (const float*)d_in[base + 4];
    const float* dwc_b  = (const float*)d_in[base + 5];
    const float* an_b   = (const float*)d_in[base + 6];
    const float* na_b   = (const float*)d_in[base + 7];
    const float* ah_b   = (const float*)d_in[base + 8];
    const float* aw_b   = (const float*)d_in[base + 9];
    const float* ha_b   = (const float*)d_in[base + 10];
    const float* wa_b   = (const float*)d_in[base + 11];
    float* out = (float*)d_out;

    cudaFuncSetAttribute(hf_gemm<false>, cudaFuncAttributeMaxDynamicSharedMemorySize, GEMM_SMEM);
    cudaFuncSetAttribute(hf_gemm<true>,  cudaFuncAttributeMaxDynamicSharedMemorySize, GEMM_SMEM);

    k_bias<<<98, 256>>>(an_b, na_b, ah_b, aw_b, ha_b, wa_b);
    k_half_w<<<(2048 * C_) / 1024, 256>>>(q_w, kv_w, proj_w);
    k_half_x<<<(int)(((size_t)MTOK * C_) / 1024), 256>>>(x);
    hf_gemm<false><<<dim3(12, MTOK / 128), 256, GEMM_SMEM>>>(nullptr, nullptr);
    k_pool<<<(B_ * AG * C_) / 256, 256>>>();
    k_agent_attn<<<dim3(NSPL, B_ * HEADS), 256>>>();
    k_agent_combine<<<B_ * HEADS, 256>>>();
    k_qattn_mma<<<dim3((NTOK + 255) / 256, B_ * HEADS), 256>>>(dwc_w, dwc_b);
    hf_gemm<true><<<dim3(4, MTOK / 128), 256, GEMM_SMEM>>>(proj_b, out);
}

// round 15
// speedup vs baseline: 4.4747x; 1.2967x over previous
#include <cuda_runtime.h>
#include <cuda_fp16.h>
#include <cstdint>
#include <math.h>

// ---------------- problem constants ----------------
constexpr int B_    = 16;
constexpr int C_    = 512;
constexpr int H_    = 56;
constexpr int W_    = 56;
constexpr int NTOK  = H_ * W_;        // 3136
constexpr int MTOK  = B_ * NTOK;      // 50176
constexpr int HEADS = 8;
constexpr int HD    = 64;
constexpr int AG    = 49;             // agent tokens

// ---------------- scratch (device globals: allocation-free) ----------------
__device__ float g_q [MTOK * C_];
__device__ float g_v [MTOK * C_];
__device__ float g_at[B_ * AG * C_];               // agent tokens
__device__ float g_av[B_ * HEADS * AG * HD];       // agent_v
__device__ float g_bias_aT[HEADS * NTOK * 64];     // pb1+pb2 transposed [h][n][a], -1e30 pad
__device__ float g_bias_q [HEADS * NTOK * AG];     // ab1 + ab2  [h][n][a]

// fp16 GEMM / attention operand buffers
__device__ __half g_xh[MTOK * C_];    // A matrix: x (qkv), then attn+dwc output (proj)
__device__ __half g_wh[2048 * C_];    // rows: 0-511 q_w, 512-1535 kv_w, 1536-2047 proj_w
__device__ __half g_qh[MTOK * C_];    // fp16 of q*0.125
__device__ __half g_kh[MTOK * C_];    // fp16 of k
__device__ __half g_vh[MTOK * C_];    // fp16 of v

// ---------------- helpers ----------------
__device__ __forceinline__ uint32_t h2_as_u32(__half2 h) {
    union { __half2 h; uint32_t u; } cvt;
    cvt.h = h;
    return cvt.u;
}
__device__ __forceinline__ uint32_t pack_half2(float a, float b) {
    return h2_as_u32(__floats2half2_rn(a, b));
}
__device__ __forceinline__ uint32_t smem_u32(const void* p) {
    uint32_t a;
    asm("{ .reg .u64 t; cvta.to.shared.u64 t, %1; cvt.u32.u64 %0, t; }" : "=r"(a) : "l"(p));
    return a;
}
#define LDSM_X4(r, addr) \
    asm volatile("ldmatrix.sync.aligned.m8n8.x4.shared.b16 {%0,%1,%2,%3}, [%4];" \
        : "=r"((r)[0]), "=r"((r)[1]), "=r"((r)[2]), "=r"((r)[3]) : "r"(addr))
#define LDSM_X4_T(r, addr) \
    asm volatile("ldmatrix.sync.aligned.m8n8.x4.trans.shared.b16 {%0,%1,%2,%3}, [%4];" \
        : "=r"((r)[0]), "=r"((r)[1]), "=r"((r)[2]), "=r"((r)[3]) : "r"(addr))

__device__ __forceinline__ void mma_f16(float c[4], const uint32_t a[4], const uint32_t b[2]) {
    asm volatile("mma.sync.aligned.m16n8k16.row.col.f32.f16.f16.f32 "
        "{%0,%1,%2,%3}, {%4,%5,%6,%7}, {%8,%9}, {%0,%1,%2,%3};"
        : "+f"(c[0]), "+f"(c[1]), "+f"(c[2]), "+f"(c[3])
        : "r"(a[0]), "r"(a[1]), "r"(a[2]), "r"(a[3]), "r"(b[0]), "r"(b[1]));
}
#define CP_ASYNC16(dst, src) \
    asm volatile("cp.async.cg.shared.global [%0], [%1], 16;" :: "r"(dst), "l"(src))
#define CP_COMMIT() asm volatile("cp.async.commit_group;")

// ---------------- convert kernels: fp32 -> fp16 ----------------
__global__ __launch_bounds__(256) void k_half_x(const float* __restrict__ src) {
    size_t i = ((size_t)blockIdx.x * 256 + threadIdx.x) * 4;
    float4 v = *(const float4*)(src + i);
    uint2 u;
    u.x = pack_half2(v.x, v.y);
    u.y = pack_half2(v.z, v.w);
    *(uint2*)(g_xh + i) = u;
}
__global__ __launch_bounds__(256) void k_half_w(const float* __restrict__ qw,
                                                const float* __restrict__ kvw,
                                                const float* __restrict__ pw) {
    size_t i = ((size_t)blockIdx.x * 256 + threadIdx.x) * 4;   // over 2048*512
    size_t row = i >> 9;
    const float* src;
    if (row < 512)        src = qw + i;
    else if (row < 1536)  src = kvw + (i - (size_t)512 * 512);
    else                  src = pw + (i - (size_t)1536 * 512);
    float4 v = *(const float4*)src;
    uint2 u;
    u.x = pack_half2(v.x, v.y);
    u.y = pack_half2(v.z, v.w);
    *(uint2*)(g_wh + i) = u;
}

// ---------------- fp16 GEMM: C(M,N) = A(M,512) * W(N,512)^T ----------------
constexpr int T_ROWB = 144;                      // 64 fp16 (128B) + 16B pad per row
constexpr int TILE_B = 128 * T_ROWB;             // 18432 B
constexpr int STAGE_B = 2 * TILE_B;              // A, B
constexpr int NSTAGE = 3;
constexpr int GEMM_SMEM = NSTAGE * STAGE_B;      // 110592 B

template <bool PROJ>
__global__ __launch_bounds__(256, 2) void hf_gemm(const float* __restrict__ pb,
                                                  float* __restrict__ out)
{
    extern __shared__ char smem[];
    const uint32_t sb = smem_u32(smem);
    const int tid = threadIdx.x;
    const int lane = tid & 31, wid = tid >> 5;
    const int warp_m = wid & 3, warp_n = wid >> 2;
    const int bm = blockIdx.y, bn = blockIdx.x;
    const int j0 = bn * 128;
    const int wrow0 = (PROJ ? 1536 : 0) + j0;
    const size_t arow0 = (size_t)bm * 128;

    float acc[2][8][4] = {};

    auto load_chunk = [&](int chunk, int stage) {
        const int k0 = chunk * 64;
        const uint32_t dstb = sb + stage * STAGE_B;
        #pragma unroll
        for (int i = 0; i < 8; i++) {
            int u = i * 256 + tid;      // 0..2047
            int t = u >> 10;            // 0 = A, 1 = B
            int s = u & 1023;
            int r = s >> 3;             // row 0..127
            int c = s & 7;              // 16B segment
            uint32_t dst = dstb + t * TILE_B + r * T_ROWB + c * 16;
            const __half* src = (t == 0)
                ? g_xh + (arow0 + r) * C_ + k0 + c * 8
                : g_wh + (size_t)(wrow0 + r) * C_ + k0 + c * 8;
            CP_ASYNC16(dst, src);
        }
        CP_COMMIT();
    };

    load_chunk(0, 0);
    load_chunk(1, 1);

    uint32_t AH[2][2][4], BH[2][4][4];
    const int ar = warp_m * 32 + (lane & 15);
    const int br = warp_n * 64 + (lane & 7) + ((lane >> 4) << 3);

    for (int ch = 0; ch < 8; ch++) {
        if (ch < 7) asm volatile("cp.async.wait_group 1;");
        else        asm volatile("cp.async.wait_group 0;");
        __syncthreads();
        if (ch + 2 < 8) load_chunk(ch + 2, (ch + 2) % NSTAGE);

        const uint32_t stb = sb + (ch % NSTAGE) * STAGE_B;
        const uint32_t ahb = stb;
        const uint32_t bhb = stb + TILE_B;

        auto ldfr = [&](int buf, int kk) {
            int acb = (kk + ((lane >> 4) << 3)) * 2;
            int bcb = (kk + (((lane >> 3) & 1) << 3)) * 2;
            #pragma unroll
            for (int mi = 0; mi < 2; mi++)
                LDSM_X4(AH[buf][mi], ahb + (ar + mi * 16) * T_ROWB + acb);
            #pragma unroll
            for (int pi = 0; pi < 4; pi++)
                LDSM_X4(BH[buf][pi], bhb + (br + pi * 16) * T_ROWB + bcb);
        };

        ldfr(0, 0);
        #pragma unroll
        for (int kk = 0; kk < 4; kk++) {
            if (kk < 3) ldfr((kk + 1) & 1, (kk + 1) * 16);
            int cb = kk & 1;
            #pragma unroll
            for (int mi = 0; mi < 2; mi++)
                #pragma unroll
                for (int ni = 0; ni < 8; ni++)
                    mma_f16(acc[mi][ni], AH[cb][mi], &BH[cb][ni >> 1][(ni & 1) * 2]);
        }
    }

    // epilogue
    {
        int qr = lane >> 2, qc = lane & 3;
        #pragma unroll
        for (int mi = 0; mi < 2; mi++) {
            #pragma unroll
            for (int ni = 0; ni < 8; ni++) {
                int row = bm * 128 + warp_m * 32 + mi * 16 + qr;
                int col = warp_n * 64 + ni * 8 + qc * 2;       // within 128-block
                float a0 = acc[mi][ni][0], a1 = acc[mi][ni][1];
                float a2 = acc[mi][ni][2], a3 = acc[mi][ni][3];
                if (PROJ) {
                    int gcol = j0 + col;
                    float b0 = pb[gcol], b1 = pb[gcol + 1];
                    *(float2*)&out[(size_t)row * 512 + gcol] = make_float2(a0 + b0, a1 + b1);
                    *(float2*)&out[(size_t)(row + 8) * 512 + gcol] = make_float2(a2 + b0, a3 + b1);
                } else if (j0 < 512) {
                    int gcol = j0 + col;
                    *(float2*)&g_q[(size_t)row * 512 + gcol] = make_float2(a0, a1);
                    *(float2*)&g_q[(size_t)(row + 8) * 512 + gcol] = make_float2(a2, a3);
                    *(uint32_t*)(g_qh + (size_t)row * 512 + gcol) =
                        pack_half2(a0 * 0.125f, a1 * 0.125f);
                    *(uint32_t*)(g_qh + (size_t)(row + 8) * 512 + gcol) =
                        pack_half2(a2 * 0.125f, a3 * 0.125f);
                } else if (j0 < 1024) {
                    int gcol = j0 - 512 + col;
                    *(uint32_t*)(g_kh + (size_t)row * 512 + gcol) = pack_half2(a0, a1);
                    *(uint32_t*)(g_kh + (size_t)(row + 8) * 512 + gcol) = pack_half2(a2, a3);
                } else {
                    int gcol = j0 - 1024 + col;
                    *(float2*)&g_v[(size_t)row * 512 + gcol] = make_float2(a0, a1);
                    *(float2*)&g_v[(size_t)(row + 8) * 512 + gcol] = make_float2(a2, a3);
                    *(uint32_t*)(g_vh + (size_t)row * 512 + gcol) = pack_half2(a0, a1);
                    *(uint32_t*)(g_vh + (size_t)(row + 8) * 512 + gcol) = pack_half2(a2, a3);
                }
            }
        }
    }
}

// ---------------- bilinear (jax.image.resize 7 -> 56, clamp-edge) ----------------
__device__ __forceinline__ float bilerp7(const float* t, int y0, int y1, float wy,
                                         int x0, int x1, float wx) {
    float v00 = t[y0 * 7 + x0], v01 = t[y0 * 7 + x1];
    float v10 = t[y1 * 7 + x0], v11 = t[y1 * 7 + x1];
    float a = v00 + (v01 - v00) * wx;
    float b = v10 + (v11 - v10) * wx;
    return a + (b - a) * wy;
}

// K0: precompute both positional-bias tables
__global__ __launch_bounds__(256) void k_bias(
    const float* __restrict__ an, const float* __restrict__ na,
    const float* __restrict__ ahb, const float* __restrict__ awb,
    const float* __restrict__ hab, const float* __restrict__ wab)
{
    int idx = blockIdx.x * 256 + threadIdx.x;          // over HEADS*NTOK = 25088
    if (idx >= HEADS * NTOK) return;
    int h = idx / NTOK;
    int n = idx % NTOK;
    int y = n / W_, x = n % W_;

    float fy = (y + 0.5f) * 0.125f - 0.5f;
    int iy = (int)floorf(fy);
    float wy = fy - (float)iy;
    int y0 = max(iy, 0), y1 = min(iy + 1, 6);

    float fx = (x + 0.5f) * 0.125f - 0.5f;
    int ix = (int)floorf(fx);
    float wx = fx - (float)ix;
    int x0 = max(ix, 0), x1 = min(ix + 1, 6);

    float* bT = g_bias_aT + ((size_t)h * NTOK + n) * 64;
    for (int a = 0; a < AG; a++) {
        const float* t1 = an + ((size_t)h * AG + a) * 49;
        float v1 = bilerp7(t1, y0, y1, wy, x0, x1, wx);
        bT[a] = v1 + ahb[((size_t)h * AG + a) * W_ + y] + awb[((size_t)h * AG + a) * W_ + x];

        const float* t2 = na + ((size_t)h * AG + a) * 49;
        float v2 = bilerp7(t2, y0, y1, wy, x0, x1, wx);
        g_bias_q[((size_t)h * NTOK + n) * AG + a] =
            v2 + hab[((size_t)h * W_ + y) * AG + a] + wab[((size_t)h * W_ + x) * AG + a];
    }
    for (int a = AG; a < 64; a++) bT[a] = -1e30f;
}

// K2: agent token pooling: 8x8 mean over q_img (B,H,W,C) -> (B,49,C)
__global__ __launch_bounds__(256) void k_pool()
{
    int idx = blockIdx.x * 256 + threadIdx.x;   // over B_*AG*C_ = 401408
    int c = idx & 511;
    int a = (idx >> 9) % AG;
    int b = idx / (AG * C_);
    int ay = a / 7, ax = a % 7;
    float s = 0.f;
    #pragma unroll
    for (int dy = 0; dy < 8; dy++)
        for (int dx = 0; dx < 8; dx++)
            s += g_q[((size_t)(b * NTOK + (ay * 8 + dy) * W_ + ax * 8 + dx)) * C_ + c];
    g_at[idx] = s * (1.0f / 64.0f);
}

// ---------------- K3: flash-style agent attention via MMA ----------------
// One CTA per (b,h). Token tiles of 256 (8 warps x 32 tokens).
// logits (tokens x 64agents) MMA -> column online-softmax -> P(fp16)@V(fp16) MMA.
// O: warp w owns agent rows (w&3)*16..+16, d cols (w>>2)*32..+32.
constexpr int AGM_AH   = 0;                 // 64*72 half = 9216 B
constexpr int AGM_V    = 9216;              // 256*72 half = 36864
constexpr int AGM_P    = 46080;             // 256*72 half = 36864
constexpr int AGM_RED  = 82944;             // 8*64 float = 2048
constexpr int AGM_M    = 84992;             // 64 float
constexpr int AGM_S    = 85248;
constexpr int AGM_MN   = 85504;
constexpr int AGM_CORR = 85760;
constexpr int AGM_SMEM = 86016;
constexpr int NT_TILES = 13;                // 13*256 = 3328 >= 3136

__global__ __launch_bounds__(256) void k_agent_mma()
{
    extern __shared__ char sm[];
    __half* s_ah = (__half*)(sm + AGM_AH);
    float*  s_red  = (float*)(sm + AGM_RED);
    float*  s_m    = (float*)(sm + AGM_M);
    float*  s_s    = (float*)(sm + AGM_S);
    float*  s_mn   = (float*)(sm + AGM_MN);
    float*  s_corr = (float*)(sm + AGM_CORR);
    const uint32_t svU = smem_u32(sm + AGM_V);
    const uint32_t spU = smem_u32(sm + AGM_P);
    const uint32_t sahU = smem_u32(sm + AGM_AH);

    int tid = threadIdx.x, w = tid >> 5, lane = tid & 31;
    int bh = blockIdx.x, b = bh >> 3, h = bh & 7;

    for (int i = tid; i < 64 * 64; i += 256) {
        int rr = i >> 6, cc = i & 63;
        s_ah[rr * 72 + cc] = (rr < AG)
            ? __float2half(g_at[((size_t)b * AG + rr) * C_ + h * HD + cc] * 0.125f)
            : __float2half(0.f);
    }
    if (tid < 64) { s_m[tid] = -1e30f; s_s[tid] = 0.f; }
    __syncthreads();

    const int r = lane >> 2, c2 = (lane & 3) * 2;
    const int lrow = (lane & 7) + ((lane >> 4) << 3);
    const int lcol = (((lane >> 3) & 1) << 3);
    const int a0 = (w & 3) * 16, d0 = (w >> 2) * 32;
    const __half* kb = g_kh + ((size_t)b * NTOK) * C_ + h * HD;

    float o[4][4] = {};

    for (int t = 0; t < NT_TILES; t++) {
        int n0 = t * 256;
        // async V tile load (fp16), rows clamped
        #pragma unroll
        for (int i = 0; i < 8; i++) {
            int u = i * 256 + tid;
            int row = u >> 3, c = u & 7;
            int tok = min(n0 + row, NTOK - 1);
            CP_ASYNC16(svU + row * 144 + c * 16,
                       g_vh + ((size_t)(b * NTOK + tok)) * C_ + h * HD + c * 8);
        }
        CP_COMMIT();

        // ---- logits MMA (tokens x agents)
        int n0w = n0 + w * 32;
        float acc[2][8][4] = {};
        #pragma unroll
        for (int ks = 0; ks < 4; ks++) {
            uint32_t BH[4][4];
            #pragma unroll
            for (int pi = 0; pi < 4; pi++)
                LDSM_X4(BH[pi], sahU + (pi * 16 + lrow) * 144 + (ks * 16 + lcol) * 2);
            #pragma unroll
            for (int mi = 0; mi < 2; mi++) {
                int t0 = n0w + mi * 16 + r;
                int ct0 = min(t0, NTOK - 1), ct1 = min(t0 + 8, NTOK - 1);
                uint32_t A[4];
                A[0] = *(const uint32_t*)(kb + (size_t)ct0 * C_ + ks * 16 + c2);
                A[1] = *(const uint32_t*)(kb + (size_t)ct1 * C_ + ks * 16 + c2);
                A[2] = *(const uint32_t*)(kb + (size_t)ct0 * C_ + ks * 16 + c2 + 8);
                A[3] = *(const uint32_t*)(kb + (size_t)ct1 * C_ + ks * 16 + c2 + 8);
                #pragma unroll
                for (int na = 0; na < 8; na++)
                    mma_f16(acc[mi][na], A, &BH[na >> 1][(na & 1) * 2]);
            }
        }

        // ---- bias + token mask (padded agents get -1e30 from bias table)
        #pragma unroll
        for (int mi = 0; mi < 2; mi++) {
            int t0 = n0w + mi * 16 + r;
            bool v0 = t0 < NTOK, v1 = (t0 + 8) < NTOK;
            const float* bp0 = g_bias_aT + ((size_t)h * NTOK + (v0 ? t0 : 0)) * 64;
            const float* bp1 = g_bias_aT + ((size_t)h * NTOK + (v1 ? t0 + 8 : 0)) * 64;
            #pragma unroll
            for (int na = 0; na < 8; na++) {
                int a = na * 8 + c2;
                if (v0) { float2 bb = *(const float2*)(bp0 + a);
                          acc[mi][na][0] += bb.x; acc[mi][na][1] += bb.y; }
                else    { acc[mi][na][0] = -1e30f; acc[mi][na][1] = -1e30f; }
                if (v1) { float2 bb = *(const float2*)(bp1 + a);
                          acc[mi][na][2] += bb.x; acc[mi][na][3] += bb.y; }
                else    { acc[mi][na][2] = -1e30f; acc[mi][na][3] = -1e30f; }
            }
        }

        // ---- column max (per agent col), warp reduce + cross-warp
        float cm[8][2];
        #pragma unroll
        for (int na = 0; na < 8; na++) {
            cm[na][0] = fmaxf(fmaxf(acc[0][na][0], acc[0][na][2]),
                              fmaxf(acc[1][na][0], acc[1][na][2]));
            cm[na][1] = fmaxf(fmaxf(acc[0][na][1], acc[0][na][3]),
                              fmaxf(acc[1][na][1], acc[1][na][3]));
            #pragma unroll
            for (int off = 4; off < 32; off <<= 1) {
                cm[na][0] = fmaxf(cm[na][0], __shfl_xor_sync(0xffffffffu, cm[na][0], off));
                cm[na][1] = fmaxf(cm[na][1], __shfl_xor_sync(0xffffffffu, cm[na][1], off));
            }
        }
        if (lane < 4) {
            #pragma unroll
            for (int na = 0; na < 8; na++) {
                s_red[w * 64 + na * 8 + c2]     = cm[na][0];
                s_red[w * 64 + na * 8 + c2 + 1] = cm[na][1];
            }
        }
        __syncthreads();
        if (tid < 64) {
            float mt = -1e30f;
            #pragma unroll
            for (int w2 = 0; w2 < 8; w2++) mt = fmaxf(mt, s_red[w2 * 64 + tid]);
            float mo = s_m[tid];
            float mn = fmaxf(mo, mt);
            s_mn[tid] = mn;
            s_corr[tid] = __expf(mo - mn);
            s_m[tid] = mn;
        }
        __syncthreads();

        // ---- P = exp(l - m), store fp16, col sums, rescale O
        float cs[8][2] = {};
        #pragma unroll
        for (int mi = 0; mi < 2; mi++) {
            int trow = w * 32 + mi * 16 + r;
            #pragma unroll
            for (int na = 0; na < 8; na++) {
                int a = na * 8 + c2;
                float mn0 = s_mn[a], mn1 = s_mn[a + 1];
                float p0 = __expf(acc[mi][na][0] - mn0);
                float p1 = __expf(acc[mi][na][1] - mn1);
                float p2 = __expf(acc[mi][na][2] - mn0);
                float p3 = __expf(acc[mi][na][3] - mn1);
                cs[na][0] += p0 + p2;
                cs[na][1] += p1 + p3;
                *(uint32_t*)(sm + AGM_P + trow * 144 + a * 2)       = pack_half2(p0, p1);
                *(uint32_t*)(sm + AGM_P + (trow + 8) * 144 + a * 2) = pack_half2(p2, p3);
            }
        }
        #pragma unroll
        for (int na = 0; na < 8; na++) {
            #pragma unroll
            for (int off = 4; off < 32; off <<= 1) {
                cs[na][0] += __shfl_xor_sync(0xffffffffu, cs[na][0], off);
                cs[na][1] += __shfl_xor_sync(0xffffffffu, cs[na][1], off);
            }
        }
        if (lane < 4) {
            #pragma unroll
            for (int na = 0; na < 8; na++) {
                s_red[w * 64 + na * 8 + c2]     = cs[na][0];
                s_red[w * 64 + na * 8 + c2 + 1] = cs[na][1];
            }
        }
        {
            float cr0 = s_corr[a0 + r], cr1 = s_corr[a0 + r + 8];
            #pragma unroll
            for (int na = 0; na < 4; na++) {
                o[na][0] *= cr0; o[na][1] *= cr0;
                o[na][2] *= cr1; o[na][3] *= cr1;
            }
        }
        __syncthreads();
        if (tid < 64) {
            float ss = 0.f;
            #pragma unroll
            for (int w2 = 0; w2 < 8; w2++) ss += s_red[w2 * 64 + tid];
            s_s[tid] = s_s[tid] * s_corr[tid] + ss;
        }
        asm volatile("cp.async.wait_group 0;");
        __syncthreads();

        // ---- PV: O[a][d] += P^T @ V  (A via ldmatrix.trans of P, B via trans of V)
        #pragma unroll 4
        for (int ks = 0; ks < 16; ks++) {
            uint32_t PA[4];
            LDSM_X4_T(PA, spU + (ks * 16 + (lane & 7) + ((lane >> 4) << 3)) * 144
                          + (a0 + (((lane >> 3) & 1) << 3)) * 2);
            uint32_t VB[2][4];
            #pragma unroll
            for (int pi = 0; pi < 2; pi++)
                LDSM_X4_T(VB[pi], svU + (ks * 16 + (lane & 7) + (((lane >> 3) & 1) << 3)) * 144
                                  + (d0 + pi * 16 + ((lane >> 4) << 3)) * 2);
            #pragma unroll
            for (int na = 0; na < 4; na++)
                mma_f16(o[na], PA, &VB[na >> 1][(na & 1) * 2]);
        }
        __syncthreads();
    }

    // ---- normalize + write agent_v
    int aa0 = a0 + r, aa1 = a0 + r + 8;
    float i0 = (aa0 < AG) ? 1.0f / s_s[aa0] : 0.f;
    float i1 = (aa1 < AG) ? 1.0f / s_s[aa1] : 0.f;
    #pragma unroll
    for (int na = 0; na < 4; na++) {
        int d = d0 + na * 8 + c2;
        if (aa0 < AG)
            *(float2*)&g_av[((size_t)bh * AG + aa0) * HD + d] =
                make_float2(o[na][0] * i0, o[na][1] * i0);
        if (aa1 < AG)
            *(float2*)&g_av[((size_t)bh * AG + aa1) * HD + d] =
                make_float2(o[na][2] * i1, o[na][3] * i1);
    }
}

// K6: q-attention via tensor-core MMA (warp = 32 tokens) + fused dwc, fp16 out -> g_xh.
__global__ __launch_bounds__(256, 2) void k_qattn_mma(const float* __restrict__ dwc_w,
                                                      const float* __restrict__ dwc_b)
{
    __shared__ __half s_ah [64 * 72];   // [agent][d]
    __shared__ __half s_avT[64 * 72];   // [d][agent]
    __shared__ float  s_w[9][64];
    __shared__ float  s_b[64];

    int tid = threadIdx.x, w = tid >> 5, lane = tid & 31;
    int bh = blockIdx.y, b = bh >> 3, h = bh & 7;

    for (int i = tid; i < 64 * 64; i += 256) {
        int rr = i >> 6, cc = i & 63;
        s_ah [rr * 72 + cc] = (rr < AG)
            ? __float2half(g_at[((size_t)b * AG + rr) * C_ + h * HD + cc]) : __float2half(0.f);
        s_avT[rr * 72 + cc] = (cc < AG)
            ? __float2half(g_av[((size_t)bh * AG + cc) * HD + rr]) : __float2half(0.f);
    }
    for (int i = tid; i < 9 * 64; i += 256)
        s_w[i / 64][i % 64] = dwc_w[(size_t)(h * 64 + (i % 64)) * 9 + i / 64];
    if (tid < 64) s_b[tid] = dwc_b[h * 64 + tid];
    __syncthreads();

    int n0w = blockIdx.x * 256 + w * 32;
    if (n0w >= NTOK) return;

    const uint32_t sah = smem_u32(s_ah), sav = smem_u32(s_avT);
    const int r = lane >> 2, c2 = (lane & 3) * 2;
    const int lrow = (lane & 7) + ((lane >> 4) << 3);
    const int lcol = (((lane >> 3) & 1) << 3);

    float acc[2][8][4] = {};
    const __half* qb = g_qh + ((size_t)(b * NTOK + n0w)) * C_ + h * HD;
    #pragma unroll
    for (int ks = 0; ks < 4; ks++) {
        uint32_t BH[4][4];
        #pragma unroll
        for (int pi = 0; pi < 4; pi++)
            LDSM_X4(BH[pi], sah + (pi * 16 + lrow) * 144 + (ks * 16 + lcol) * 2);
        #pragma unroll
        for (int mi = 0; mi < 2; mi++) {
            const __half* qq = qb + (size_t)(mi * 16 + r) * C_ + ks * 16 + c2;
            uint32_t A[4];
            A[0] = *(const uint32_t*)(qq);
            A[1] = *(const uint32_t*)(qq + 8 * C_);
            A[2] = *(const uint32_t*)(qq + 8);
            A[3] = *(const uint32_t*)(qq + 8 * C_ + 8);
            #pragma unroll
            for (int na = 0; na < 8; na++)
                mma_f16(acc[mi][na], A, &BH[na >> 1][(na & 1) * 2]);
        }
    }

    uint32_t pa[2][8][2];
    #pragma unroll
    for (int mi = 0; mi < 2; mi++) {
        int t0 = n0w + mi * 16 + r;
        float m0 = -1e30f, m1 = -1e30f;
        #pragma unroll
        for (int na = 0; na < 8; na++) {
            int a0 = na * 8 + c2;
            if (a0 < AG) {
                const float* bp0 = g_bias_q + ((size_t)h * NTOK + t0) * AG + a0;
                const float* bp1 = g_bias_q + ((size_t)h * NTOK + t0 + 8) * AG + a0;
                acc[mi][na][0] += bp0[0];
                acc[mi][na][2] += bp1[0];
                if (a0 + 1 < AG) { acc[mi][na][1] += bp0[1]; acc[mi][na][3] += bp1[1]; }
                else             { acc[mi][na][1] = -1e30f;  acc[mi][na][3] = -1e30f; }
            } else {
                acc[mi][na][0] = acc[mi][na][1] = -1e30f;
                acc[mi][na][2] = acc[mi][na][3] = -1e30f;
            }
            m0 = fmaxf(m0, fmaxf(acc[mi][na][0], acc[mi][na][1]));
            m1 = fmaxf(m1, fmaxf(acc[mi][na][2], acc[mi][na][3]));
        }
        m0 = fmaxf(m0, __shfl_xor_sync(0xffffffffu, m0, 1));
        m0 = fmaxf(m0, __shfl_xor_sync(0xffffffffu, m0, 2));
        m1 = fmaxf(m1, __shfl_xor_sync(0xffffffffu, m1, 1));
        m1 = fmaxf(m1, __shfl_xor_sync(0xffffffffu, m1, 2));
        float s0 = 0.f, s1 = 0.f;
        #pragma unroll
        for (int na = 0; na < 8; na++) {
            acc[mi][na][0] = __expf(acc[mi][na][0] - m0);
            acc[mi][na][1] = __expf(acc[mi][na][1] - m0);
            acc[mi][na][2] = __expf(acc[mi][na][2] - m1);
            acc[mi][na][3] = __expf(acc[mi][na][3] - m1);
            s0 += acc[mi][na][0] + acc[mi][na][1];
            s1 += acc[mi][na][2] + acc[mi][na][3];
        }
        s0 += __shfl_xor_sync(0xffffffffu, s0, 1);
        s0 += __shfl_xor_sync(0xffffffffu, s0, 2);
        s1 += __shfl_xor_sync(0xffffffffu, s1, 1);
        s1 += __shfl_xor_sync(0xffffffffu, s1, 2);
        float i0 = 1.0f / s0, i1 = 1.0f / s1;
        #pragma unroll
        for (int na = 0; na < 8; na++) {
            pa[mi][na][0] = pack_half2(acc[mi][na][0] * i0, acc[mi][na][1] * i0);
            pa[mi][na][1] = pack_half2(acc[mi][na][2] * i1, acc[mi][na][3] * i1);
        }
    }

    float o[2][8][4] = {};
    #pragma unroll
    for (int ks = 0; ks < 4; ks++) {
        uint32_t BH[4][4];
        #pragma unroll
        for (int pi = 0; pi < 4; pi++)
            LDSM_X4(BH[pi], sav + (pi * 16 + lrow) * 144 + (ks * 16 + lcol) * 2);
        #pragma unroll
        for (int mi = 0; mi < 2; mi++) {
            uint32_t A[4] = { pa[mi][2 * ks][0], pa[mi][2 * ks][1],
                              pa[mi][2 * ks + 1][0], pa[mi][2 * ks + 1][1] };
            #pragma unroll
            for (int na = 0; na < 8; na++)
                mma_f16(o[mi][na], A, &BH[na >> 1][(na & 1) * 2]);
        }
    }

    #pragma unroll
    for (int mi = 0; mi < 2; mi++) {
        #pragma unroll
        for (int rh = 0; rh < 2; rh++) {
            int t = n0w + mi * 16 + r + rh * 8;
            int y = t / W_, x = t % W_;
            float v0[8], v1[8];
            #pragma unroll
            for (int na = 0; na < 8; na++) {
                v0[na] = o[mi][na][rh * 2 + 0] + s_b[na * 8 + c2];
                v1[na] = o[mi][na][rh * 2 + 1] + s_b[na * 8 + c2 + 1];
            }
            #pragma unroll
            for (int dy = -1; dy <= 1; dy++) {
                int yy = y + dy;
                if (yy < 0 || yy >= H_) continue;
                #pragma unroll
                for (int dx = -1; dx <= 1; dx++) {
                    int xx = x + dx;
                    if (xx < 0 || xx >= W_) continue;
                    int j = (dy + 1) * 3 + (dx + 1);
                    const float* vb = g_v + ((size_t)(b * NTOK + yy * W_ + xx)) * C_ + h * HD;
                    #pragma unroll
                    for (int na = 0; na < 8; na++) {
                        float2 vv = *(const float2*)(vb + na * 8 + c2);
                        float2 ww = *(const float2*)(&s_w[j][na * 8 + c2]);
                        v0[na] += vv.x * ww.x;
                        v1[na] += vv.y * ww.y;
                    }
                }
            }
            __half* ob = g_xh + ((size_t)(b * NTOK + t)) * C_ + h * HD;
            #pragma unroll
            for (int na = 0; na < 8; na++)
                *(uint32_t*)(ob + na * 8 + c2) = pack_half2(v0[na], v1[na]);
        }
    }
}

// ---------------- launch ----------------
extern "C" void kernel_launch(void* const* d_in, const int* in_sizes, int n_in,
                              void* d_out, int out_size)
{
    int base = (n_in >= 15 && in_sizes[1] == 1) ? 3 : 1;

    const float* x      = (const float*)d_in[0];
    const float* q_w    = (const float*)d_in[base + 0];
    const float* kv_w   = (const float*)d_in[base + 1];
    const float* proj_w = (const float*)d_in[base + 2];
    const float* proj_b = (const float*)d_in[base + 3];
    const float* dwc_w  = (const float*)d_in[base + 4];
    const float* dwc_b  = (const float*)d_in[base + 5];
    const float* an_b   = (const float*)d_in[base + 6];
    const float* na_b   = (const float*)d_in[base + 7];
    const float* ah_b   = (const float*)d_in[base + 8];
    const float* aw_b   = (const float*)d_in[base + 9];
    const float* ha_b   = (const float*)d_in[base + 10];
    const float* wa_b   = (const float*)d_in[base + 11];
    float* out = (float*)d_out;

    cudaFuncSetAttribute(hf_gemm<false>, cudaFuncAttributeMaxDynamicSharedMemorySize, GEMM_SMEM);
    cudaFuncSetAttribute(hf_gemm<true>,  cudaFuncAttributeMaxDynamicSharedMemorySize, GEMM_SMEM);
    cudaFuncSetAttribute(k_agent_mma,    cudaFuncAttributeMaxDynamicSharedMemorySize, AGM_SMEM);

    k_bias<<<98, 256>>>(an_b, na_b, ah_b, aw_b, ha_b, wa_b);
    k_half_w<<<(2048 * C_) / 1024, 256>>>(q_w, kv_w, proj_w);
    k_half_x<<<(int)(((size_t)MTOK * C_) / 1024), 256>>>(x);
    hf_gemm<false><<<dim3(12, MTOK / 128), 256, GEMM_SMEM>>>(nullptr, nullptr);
    k_pool<<<(B_ * AG * C_) / 256, 256>>>();
    k_agent_mma<<<B_ * HEADS, 256, AGM_SMEM>>>();
    k_qattn_mma<<<dim3((NTOK + 255) / 256, B_ * HEADS), 256>>>(dwc_w, dwc_b);
    hf_gemm<true><<<dim3(4, MTOK / 128), 256, GEMM_SMEM>>>(proj_b, out);
}